// round 3
// baseline (speedup 1.0000x reference)
#include <cuda_runtime.h>
#include <math.h>

#define TWO_PI_F 6.283185307179586f

// ---------------------------------------------------------------------------
// Scratch layout (single __device__ array, no allocations anywhere)
// B-set: post-conv per-layer arrays, stride NBUF = max B*Co*Nconv = 8*16*1280
//   0:w 1:p0 2:p1 3:c00 4:c01 5:c11 6:q00 7:q01 8:q11 9:det 10:score
//   (q = -0.5 * inv(C) with the 2x factor folded into q01)
// A-set: post-topk / normalized layer-data arrays, stride NA
//   0:w 1:p0 2:p1 3:c00 4:c01 5:c11
// X: integrated class scores [B*10]
// ---------------------------------------------------------------------------
constexpr int NBUF = 163840;
constexpr int NA   = 16384;

__device__ float g_scratch[11*(size_t)NBUF + 6*(size_t)NA + 128];

__device__ __forceinline__ float* bufB(int k){ return g_scratch + (size_t)k*NBUF; }
__device__ __forceinline__ float* bufA(int k){ return g_scratch + 11*(size_t)NBUF + (size_t)k*NA; }
__device__ __forceinline__ float* bufX(){ return g_scratch + 11*(size_t)NBUF + 6*(size_t)NA; }

// ---------------------------------------------------------------------------
// norm0: per-sample CovScaleNorm + WeightNorm on the input GM (L=1, N=128)
// ---------------------------------------------------------------------------
__global__ void norm0_kernel(const float* __restrict__ in_w,
                             const float* __restrict__ in_p,
                             const float* __restrict__ in_c)
{
    const int N = 128;
    int b = blockIdx.x, t = threadIdx.x;
    int gi = b*N + t;
    float w  = in_w[gi];
    float px = in_p[gi*2+0], py = in_p[gi*2+1];
    float a  = in_c[gi*4+0], o = in_c[gi*4+1], c = in_c[gi*4+3];

    __shared__ float red[128];
    __shared__ float sval;

    red[t] = 0.5f*(a + c); __syncthreads();
    for (int s = N/2; s > 0; s >>= 1){ if (t < s) red[t] += red[t+s]; __syncthreads(); }
    if (t == 0) sval = rsqrtf(red[0]/(float)N + 1e-8f);
    __syncthreads();
    float f = sval, f2 = f*f;
    px *= f; py *= f; a *= f2; o *= f2; c *= f2;

    float det = a*c - o*o;
    float iv  = fabsf(w)*TWO_PI_F*sqrtf(fmaxf(det, 1e-12f));
    __syncthreads();
    red[t] = iv; __syncthreads();
    for (int s = N/2; s > 0; s >>= 1){ if (t < s) red[t] += red[t+s]; __syncthreads(); }
    if (t == 0) sval = red[0]/(float)N + 1e-6f;
    __syncthreads();
    w /= sval;

    bufA(0)[gi]=w;  bufA(1)[gi]=px; bufA(2)[gi]=py;
    bufA(3)[gi]=a;  bufA(4)[gi]=o;  bufA(5)[gi]=c;
}

// ---------------------------------------------------------------------------
// gm_convolve: data GM (A-set, [B,Ci,Nd]) x kernel GM -> B-set [B,Co,Ci*Nd*Nk]
// Also emits the folded -0.5*inv(cov) and det(cov) for the eval stage.
// ---------------------------------------------------------------------------
__global__ void conv_kernel(int B, int Ci, int Nd, int Co, int Nk,
                            const float* __restrict__ kw,
                            const float* __restrict__ kp,
                            const float* __restrict__ kc)
{
    int Nc = Ci*Nd*Nk;
    int total = B*Co*Nc;
    int gid = blockIdx.x*blockDim.x + threadIdx.x;
    if (gid >= total) return;
    int n  = gid % Nc;  int t  = gid / Nc;
    int co = t % Co;    int b  = t / Co;
    int nk = n % Nk;    int t2 = n / Nk;
    int nd = t2 % Nd;   int ci = t2 / Nd;

    int di = (b*Ci + ci)*Nd + nd;
    int ki = (co*Ci + ci)*Nk + nk;

    float d00=bufA(3)[di], d01=bufA(4)[di], d11=bufA(5)[di];
    float k00=kc[ki*4+0],  k01=kc[ki*4+1],  k11=kc[ki*4+3];
    float s00=d00+k00, s01=d01+k01, s11=d11+k11;

    float det_d = d00*d11 - d01*d01;
    float det_k = k00*k11 - k01*k01;
    float det_s = s00*s11 - s01*s01;
    float r   = det_d*det_k / fmaxf(det_s, 1e-12f);
    float amp = TWO_PI_F * sqrtf(fmaxf(r, 1e-20f));
    float wv  = bufA(0)[di]*kw[ki]*amp;
    float inv = 1.0f/det_s;

    size_t oi = (size_t)(b*Co+co)*Nc + n;
    bufB(0)[oi] = wv;
    bufB(1)[oi] = bufA(1)[di] + kp[ki*2+0];
    bufB(2)[oi] = bufA(2)[di] + kp[ki*2+1];
    bufB(3)[oi] = s00; bufB(4)[oi] = s01; bufB(5)[oi] = s11;
    bufB(6)[oi] = -0.5f*s11*inv;   // -0.5*P00
    bufB(7)[oi] =  s01*inv;        // -P01 (2x factor folded)
    bufB(8)[oi] = -0.5f*s00*inv;   // -0.5*P11
    bufB(9)[oi] = det_s;
}

// ---------------------------------------------------------------------------
// Eval-at-centers + relu_fit weight scaling + top-k score. One block per
// (b, co) pair. All j-data staged in shared (broadcast reads), IPT
// i-accumulators per thread amortize shared loads.
// ---------------------------------------------------------------------------
template<int N, int BLOCK, int IPT>
__global__ void __launch_bounds__(BLOCK) eval_kernel()
{
    static_assert(N == BLOCK*IPT, "exact tiling expected");
    size_t base = (size_t)blockIdx.x * N;
    __shared__ float4 sA [N];   // (w, q00, q01, q11)
    __shared__ float2 sMu[N];

    const float* w = bufB(0);
    for (int j = threadIdx.x; j < N; j += BLOCK){
        sA [j] = make_float4(w[base+j], bufB(6)[base+j], bufB(7)[base+j], bufB(8)[base+j]);
        sMu[j] = make_float2(bufB(1)[base+j], bufB(2)[base+j]);
    }
    __syncthreads();

    float acc[IPT], mx[IPT], my[IPT];
    #pragma unroll
    for (int k = 0; k < IPT; k++){
        int i = threadIdx.x + k*BLOCK;
        acc[k] = 0.f; mx[k] = sMu[i].x; my[k] = sMu[i].y;
    }

    #pragma unroll 2
    for (int j = 0; j < N; j++){
        float4 a = sA[j]; float2 m = sMu[j];
        #pragma unroll
        for (int k = 0; k < IPT; k++){
            float dx = mx[k] - m.x;
            float dy = my[k] - m.y;
            float u  = fmaf(a.y, dx, a.z*dy);
            float q  = fmaf(u,   dx, a.w*dy*dy);   // -0.5 * dx^T P dx
            acc[k]   = fmaf(a.x, __expf(q), acc[k]);
        }
    }

    #pragma unroll
    for (int k = 0; k < IPT; k++){
        int i = threadIdx.x + k*BLOCK;
        float s = acc[k];
        float denom = (fabsf(s) > 1e-6f) ? s : 1e-6f;
        float wn = w[base+i] * (fmaxf(s, 0.f)/denom);
        bufB(0)[base+i]  = wn;
        bufB(10)[base+i] = fabsf(wn)*sqrtf(fmaxf(bufB(9)[base+i], 1e-12f));
    }
}

// ---------------------------------------------------------------------------
// top-k selection (k sequential argmax passes, jax-stable lowest-index ties),
// gathers the selected components into the A-set.
// ---------------------------------------------------------------------------
__global__ void topk_kernel(int N, int K)
{
    int pair = blockIdx.x;
    size_t ib = (size_t)pair*N, ob = (size_t)pair*K;
    __shared__ float sc[1280];
    __shared__ int   sel[32];
    __shared__ float rv[8];
    __shared__ int   ri[8];
    const int BLOCK = blockDim.x;

    for (int j = threadIdx.x; j < N; j += BLOCK) sc[j] = bufB(10)[ib+j];
    __syncthreads();

    int lane = threadIdx.x & 31, wid = threadIdx.x >> 5;
    for (int it = 0; it < K; it++){
        float bv = -1.f; int bi = 1 << 30;
        for (int j = threadIdx.x; j < N; j += BLOCK){
            float v = sc[j];
            if (v > bv || (v == bv && j < bi)){ bv = v; bi = j; }
        }
        for (int off = 16; off; off >>= 1){
            float ov = __shfl_down_sync(0xffffffffu, bv, off);
            int   oi = __shfl_down_sync(0xffffffffu, bi, off);
            if (ov > bv || (ov == bv && oi < bi)){ bv = ov; bi = oi; }
        }
        if (lane == 0){ rv[wid] = bv; ri[wid] = bi; }
        __syncthreads();
        if (threadIdx.x == 0){
            int nw = BLOCK >> 5;
            for (int u = 1; u < nw; u++){
                if (rv[u] > bv || (rv[u] == bv && ri[u] < bi)){ bv = rv[u]; bi = ri[u]; }
            }
            sel[it] = bi;
            sc[bi]  = -2.f;   // scores are >= 0; mark consumed
        }
        __syncthreads();
    }

    for (int t = threadIdx.x; t < K; t += BLOCK){
        int idx = sel[t];
        bufA(0)[ob+t] = bufB(0)[ib+idx];
        bufA(1)[ob+t] = bufB(1)[ib+idx];
        bufA(2)[ob+t] = bufB(2)[ib+idx];
        bufA(3)[ob+t] = bufB(3)[ib+idx];
        bufA(4)[ob+t] = bufB(4)[ib+idx];
        bufA(5)[ob+t] = bufB(5)[ib+idx];
    }
}

// ---------------------------------------------------------------------------
// Channel-wise (batch_norm=True) CovScaleNorm + WeightBatchNorm.
// One block per channel l; stats over all (b, n).
// ---------------------------------------------------------------------------
__global__ void norm_channel_kernel(int setB, int B, int L, int N)
{
    float* w   = setB ? bufB(0) : bufA(0);
    float* p0  = setB ? bufB(1) : bufA(1);
    float* p1  = setB ? bufB(2) : bufA(2);
    float* c00 = setB ? bufB(3) : bufA(3);
    float* c01 = setB ? bufB(4) : bufA(4);
    float* c11 = setB ? bufB(5) : bufA(5);

    int l = blockIdx.x;
    int M = B*N;
    __shared__ float red[256];
    __shared__ float sval;

    float sum = 0.f;
    for (int e = threadIdx.x; e < M; e += blockDim.x){
        int b = e/N, n = e - b*N; size_t idx = ((size_t)(b*L+l))*N + n;
        sum += 0.5f*(c00[idx] + c11[idx]);
    }
    red[threadIdx.x] = sum; __syncthreads();
    for (int s = blockDim.x >> 1; s; s >>= 1){
        if (threadIdx.x < s) red[threadIdx.x] += red[threadIdx.x+s];
        __syncthreads();
    }
    if (threadIdx.x == 0) sval = rsqrtf(red[0]/(float)M + 1e-8f);
    __syncthreads();
    float f = sval, f2 = f*f;

    float sum2 = 0.f;
    for (int e = threadIdx.x; e < M; e += blockDim.x){
        int b = e/N, n = e - b*N; size_t idx = ((size_t)(b*L+l))*N + n;
        p0[idx] *= f; p1[idx] *= f;
        float a = c00[idx]*f2, o = c01[idx]*f2, c = c11[idx]*f2;
        c00[idx] = a; c01[idx] = o; c11[idx] = c;
        float det = a*c - o*o;
        sum2 += fabsf(w[idx])*TWO_PI_F*sqrtf(fmaxf(det, 1e-12f));
    }
    __syncthreads();
    red[threadIdx.x] = sum2; __syncthreads();
    for (int s = blockDim.x >> 1; s; s >>= 1){
        if (threadIdx.x < s) red[threadIdx.x] += red[threadIdx.x+s];
        __syncthreads();
    }
    if (threadIdx.x == 0) sval = red[0]/(float)M + 1e-6f;
    __syncthreads();
    float scale = sval;
    for (int e = threadIdx.x; e < M; e += blockDim.x){
        int b = e/N, n = e - b*N; size_t idx = ((size_t)(b*L+l))*N + n;
        w[idx] /= scale;
    }
}

// ---------------------------------------------------------------------------
// gm.integrate: x[b, cls] = sum_n w * 2pi * sqrt(clip(det C, 1e-12))
// ---------------------------------------------------------------------------
__global__ void integrate_kernel(int N)
{
    size_t base = (size_t)blockIdx.x * N;
    __shared__ float red[256];
    float s = 0.f;
    for (int n = threadIdx.x; n < N; n += blockDim.x){
        float det = bufB(3)[base+n]*bufB(5)[base+n] - bufB(4)[base+n]*bufB(4)[base+n];
        s += bufB(0)[base+n]*TWO_PI_F*sqrtf(fmaxf(det, 1e-12f));
    }
    red[threadIdx.x] = s; __syncthreads();
    for (int t = blockDim.x >> 1; t; t >>= 1){
        if (threadIdx.x < t) red[threadIdx.x] += red[threadIdx.x+t];
        __syncthreads();
    }
    if (threadIdx.x == 0) bufX()[blockIdx.x] = red[0];
}

// ---------------------------------------------------------------------------
// Final BatchNorm1d (training mode) over batch + log_softmax over classes.
// ---------------------------------------------------------------------------
__global__ void final_kernel(float* __restrict__ out)
{
    __shared__ float sx[80], sn2[80];
    int t = threadIdx.x;
    if (t < 80) sx[t] = bufX()[t];
    __syncthreads();
    if (t < 10){
        float mu = 0.f;
        for (int b = 0; b < 8; b++) mu += sx[b*10+t];
        mu *= 0.125f;
        float var = 0.f;
        for (int b = 0; b < 8; b++){ float d = sx[b*10+t] - mu; var += d*d; }
        var *= 0.125f;
        float iv = rsqrtf(var + 1e-5f);
        for (int b = 0; b < 8; b++) sn2[b*10+t] = (sx[b*10+t] - mu)*iv;
    }
    __syncthreads();
    if (t < 8){
        float mx = -1e30f;
        for (int c = 0; c < 10; c++) mx = fmaxf(mx, sn2[t*10+c]);
        float se = 0.f;
        for (int c = 0; c < 10; c++) se += expf(sn2[t*10+c] - mx);
        float lse = mx + logf(se);
        for (int c = 0; c < 10; c++) out[t*10+c] = sn2[t*10+c] - lse;
    }
}

// ---------------------------------------------------------------------------
extern "C" void kernel_launch(void* const* d_in, const int* in_sizes, int n_in,
                              void* d_out, int out_size)
{
    const float* in_w = (const float*)d_in[0];
    const float* in_p = (const float*)d_in[1];
    const float* in_c = (const float*)d_in[2];
    const float* k0w  = (const float*)d_in[3];
    const float* k0p  = (const float*)d_in[4];
    const float* k0c  = (const float*)d_in[5];
    const float* k1w  = (const float*)d_in[6];
    const float* k1p  = (const float*)d_in[7];
    const float* k1c  = (const float*)d_in[8];
    const float* k2w  = (const float*)d_in[9];
    const float* k2p  = (const float*)d_in[10];
    const float* k2c  = (const float*)d_in[11];
    float* out = (float*)d_out;

    // norm0: per-sample stats on input GM
    norm0_kernel<<<8, 128>>>(in_w, in_p, in_c);

    // ---- layer 0: Ci=1, Nd=128, Co=8, Nk=5 -> Nconv=640, n_fit=32 ----
    conv_kernel<<<(8*8*640 + 255)/256, 256>>>(8, 1, 128, 8, 5, k0w, k0p, k0c);
    eval_kernel<640, 128, 5><<<64, 128>>>();
    topk_kernel<<<64, 256>>>(640, 32);
    norm_channel_kernel<<<8, 256>>>(0, 8, 8, 32);

    // ---- layer 1: Ci=8, Nd=32, Co=16, Nk=5 -> Nconv=1280, n_fit=16 ----
    conv_kernel<<<(8*16*1280 + 255)/256, 256>>>(8, 8, 32, 16, 5, k1w, k1p, k1c);
    eval_kernel<1280, 256, 5><<<128, 256>>>();
    topk_kernel<<<128, 256>>>(1280, 16);
    norm_channel_kernel<<<16, 256>>>(0, 8, 16, 16);

    // ---- layer 2: Ci=16, Nd=16, Co=10, Nk=5 -> Nconv=1280, keep all ----
    conv_kernel<<<(8*10*1280 + 255)/256, 256>>>(8, 16, 16, 10, 5, k2w, k2p, k2c);
    eval_kernel<1280, 256, 5><<<80, 256>>>();
    norm_channel_kernel<<<10, 256>>>(1, 8, 10, 1280);

    // ---- integrate + BatchNorm1d + log_softmax ----
    integrate_kernel<<<80, 256>>>(1280);
    final_kernel<<<1, 128>>>(out);
}

// round 4
// speedup vs baseline: 1.2907x; 1.2907x over previous
#include <cuda_runtime.h>
#include <math.h>

#define TWO_PI_F 6.283185307179586f

// ---------------------------------------------------------------------------
// Scratch (single __device__ array):
//   gW,gP0,gP1,gC00,gC01,gC11 : per-pair conv components, stride NBUF
//   gAcc[4]                   : slotted eval partial sums (deterministic)
//   gA[6]                     : layer-data set (post-topk / normalized)
//   gX                        : integrated class scores [8*10]
// ---------------------------------------------------------------------------
constexpr int NBUF = 163840;   // max pairs*N = 128*1280 (layer1)
constexpr int NA   = 2048;     // max B*Co*K

__device__ float g_scratch[(size_t)10*NBUF + 6*NA + 128];

__device__ __forceinline__ float* gW()        { return g_scratch + 0*(size_t)NBUF; }
__device__ __forceinline__ float* gP0()       { return g_scratch + 1*(size_t)NBUF; }
__device__ __forceinline__ float* gP1()       { return g_scratch + 2*(size_t)NBUF; }
__device__ __forceinline__ float* gC00()      { return g_scratch + 3*(size_t)NBUF; }
__device__ __forceinline__ float* gC01()      { return g_scratch + 4*(size_t)NBUF; }
__device__ __forceinline__ float* gC11()      { return g_scratch + 5*(size_t)NBUF; }
__device__ __forceinline__ float* gAcc(int c) { return g_scratch + (size_t)(6+c)*NBUF; }
__device__ __forceinline__ float* gA(int k)   { return g_scratch + 10*(size_t)NBUF + (size_t)k*NA; }
__device__ __forceinline__ float* gX()        { return g_scratch + 10*(size_t)NBUF + 6*(size_t)NA; }

// ---------------------------------------------------------------------------
// norm0: per-sample CovScaleNorm + WeightNorm on input GM (L=1, N=128)
// ---------------------------------------------------------------------------
__global__ void norm0_kernel(const float* __restrict__ in_w,
                             const float* __restrict__ in_p,
                             const float* __restrict__ in_c)
{
    const int N = 128;
    int b = blockIdx.x, t = threadIdx.x;
    int gi = b*N + t;
    float w  = in_w[gi];
    float px = in_p[gi*2+0], py = in_p[gi*2+1];
    float a  = in_c[gi*4+0], o = in_c[gi*4+1], c = in_c[gi*4+3];

    __shared__ float red[128];
    __shared__ float sval;

    red[t] = 0.5f*(a + c); __syncthreads();
    for (int s = N/2; s > 0; s >>= 1){ if (t < s) red[t] += red[t+s]; __syncthreads(); }
    if (t == 0) sval = rsqrtf(red[0]/(float)N + 1e-8f);
    __syncthreads();
    float f = sval, f2 = f*f;
    px *= f; py *= f; a *= f2; o *= f2; c *= f2;

    float det = a*c - o*o;
    float iv  = fabsf(w)*TWO_PI_F*sqrtf(fmaxf(det, 1e-12f));
    __syncthreads();
    red[t] = iv; __syncthreads();
    for (int s = N/2; s > 0; s >>= 1){ if (t < s) red[t] += red[t+s]; __syncthreads(); }
    if (t == 0) sval = red[0]/(float)N + 1e-6f;
    __syncthreads();
    w /= sval;

    gA(0)[gi]=w;  gA(1)[gi]=px; gA(2)[gi]=py;
    gA(3)[gi]=a;  gA(4)[gi]=o;  gA(5)[gi]=c;
}

// ---------------------------------------------------------------------------
// Fused conv + eval-at-centers (chunked over j). One block per (pair, chunk).
// Stages its j-chunk's conv output in shared (w, -0.5*invC folded, mu), writes
// component data (w,p,C) for its chunk to global, accumulates partial eval
// sums for ALL i into gAcc[chunk].
// ---------------------------------------------------------------------------
template<int Ci, int Nd, int Co, int Nk, int N, int CH, int BLOCK, int IPT>
__global__ void __launch_bounds__(BLOCK) eval_fused_kernel(
    const float* __restrict__ kw, const float* __restrict__ kp,
    const float* __restrict__ kc)
{
    static_assert(N == BLOCK*IPT, "i tiling");
    constexpr int NJ = N / CH;
    int pair  = blockIdx.x / CH;
    int chunk = blockIdx.x - pair*CH;
    int b  = pair / Co;
    int co = pair - b*Co;
    size_t base = (size_t)pair * N;

    __shared__ float4 sA [NJ];   // (w, -0.5*P00, -P01, -0.5*P11)
    __shared__ float2 sMu[NJ];

    const float* Aw  = gA(0); const float* Ap0 = gA(1); const float* Ap1 = gA(2);
    const float* Ac00= gA(3); const float* Ac01= gA(4); const float* Ac11= gA(5);

    for (int jj = threadIdx.x; jj < NJ; jj += BLOCK){
        int n  = chunk*NJ + jj;
        int nk = n % Nk;  int t2 = n / Nk;
        int nd = t2 % Nd; int ci = t2 / Nd;
        int di = (b*Ci + ci)*Nd + nd;
        int ki = (co*Ci + ci)*Nk + nk;

        float d00=Ac00[di], d01=Ac01[di], d11=Ac11[di];
        float k00=kc[ki*4+0], k01=kc[ki*4+1], k11=kc[ki*4+3];
        float s00=d00+k00, s01=d01+k01, s11=d11+k11;

        float det_d = d00*d11 - d01*d01;
        float det_k = k00*k11 - k01*k01;
        float det_s = s00*s11 - s01*s01;
        float amp = TWO_PI_F * sqrtf(fmaxf(det_d*det_k/fmaxf(det_s,1e-12f), 1e-20f));
        float wv  = Aw[di]*kw[ki]*amp;
        float px  = Ap0[di] + kp[ki*2+0];
        float py  = Ap1[di] + kp[ki*2+1];
        float inv = 1.0f/det_s;

        sA [jj] = make_float4(wv, -0.5f*s11*inv, s01*inv, -0.5f*s00*inv);
        sMu[jj] = make_float2(px, py);

        gW()  [base+n] = wv;
        gP0() [base+n] = px;  gP1() [base+n] = py;
        gC00()[base+n] = s00; gC01()[base+n] = s01; gC11()[base+n] = s11;
    }
    __syncthreads();

    float acc[IPT], mx[IPT], my[IPT];
    #pragma unroll
    for (int k = 0; k < IPT; k++){
        int i  = threadIdx.x + k*BLOCK;
        int nk = i % Nk;  int t2 = i / Nk;
        int nd = t2 % Nd; int ci = t2 / Nd;
        int di = (b*Ci + ci)*Nd + nd;
        int ki = (co*Ci + ci)*Nk + nk;
        mx[k] = Ap0[di] + kp[ki*2+0];
        my[k] = Ap1[di] + kp[ki*2+1];
        acc[k] = 0.f;
    }

    #pragma unroll 2
    for (int jj = 0; jj < NJ; jj++){
        float4 a = sA[jj]; float2 m = sMu[jj];
        #pragma unroll
        for (int k = 0; k < IPT; k++){
            float dx = mx[k] - m.x;
            float dy = my[k] - m.y;
            float u  = fmaf(a.y, dx, a.z*dy);
            float q  = fmaf(u,   dx, a.w*dy*dy);   // -0.5 * d^T P d
            acc[k]   = fmaf(a.x, __expf(q), acc[k]);
        }
    }

    float* out = gAcc(chunk);
    #pragma unroll
    for (int k = 0; k < IPT; k++)
        out[base + threadIdx.x + k*BLOCK] = acc[k];
}

// ---------------------------------------------------------------------------
// Fused: relu_fit finalize + top-k (warp per (b)-pair, no block barriers in
// the K loop) + channel-wise CovScaleNorm + WeightBatchNorm. Block per co.
// ---------------------------------------------------------------------------
template<int Co, int N, int K, int CH>
__global__ void __launch_bounds__(256) topknorm_kernel()
{
    constexpr int B = 8, BLOCK = 256;
    int co = blockIdx.x, tid = threadIdx.x;

    __shared__ float sSc[B*N];
    __shared__ int   sel[B*K];
    __shared__ float red[BLOCK];
    __shared__ float sF, sWS;

    // finalize s -> w_new, score
    for (int e = tid; e < B*N; e += BLOCK){
        int b = e / N, n = e - b*N;
        size_t idx = (size_t)(b*Co + co)*N + n;
        float s = 0.f;
        #pragma unroll
        for (int c = 0; c < CH; c++) s += gAcc(c)[idx];
        float w = gW()[idx];
        float denom = (fabsf(s) > 1e-6f) ? s : 1e-6f;
        float wn = w * (fmaxf(s, 0.f)/denom);
        gW()[idx] = wn;
        float c00 = gC00()[idx], c01 = gC01()[idx], c11 = gC11()[idx];
        float det = c00*c11 - c01*c01;
        sSc[e] = fabsf(wn)*sqrtf(fmaxf(det, 1e-12f));
    }
    __syncthreads();

    // top-k: warp w handles pair b=w (scores >= 0; -2 marks consumed)
    int lane = tid & 31, wid = tid >> 5;
    float* sc = sSc + wid*N;
    for (int it = 0; it < K; it++){
        float bv = -1.f; int bi = 1 << 30;
        for (int j = lane; j < N; j += 32){
            float v = sc[j];
            if (v > bv || (v == bv && j < bi)){ bv = v; bi = j; }
        }
        #pragma unroll
        for (int off = 16; off; off >>= 1){
            float ov = __shfl_down_sync(0xffffffffu, bv, off);
            int   oi = __shfl_down_sync(0xffffffffu, bi, off);
            if (ov > bv || (ov == bv && oi < bi)){ bv = ov; bi = oi; }
        }
        if (lane == 0){ sel[wid*K + it] = bi; sc[bi] = -2.f; }
        __syncwarp();
    }
    __syncthreads();

    // cov-scale stats over selected (B*K <= 256)
    float tr = 0.f;
    if (tid < B*K){
        int b = tid / K; int n = sel[tid];
        size_t idx = (size_t)(b*Co + co)*N + n;
        tr = 0.5f*(gC00()[idx] + gC11()[idx]);
    }
    red[tid] = tr; __syncthreads();
    for (int s = BLOCK>>1; s; s >>= 1){ if (tid < s) red[tid] += red[tid+s]; __syncthreads(); }
    if (tid == 0) sF = rsqrtf(red[0]/(float)(B*K) + 1e-8f);
    __syncthreads();
    float f = sF, f2 = f*f;

    // weight-norm scale with SCALED covariances
    float ab = 0.f;
    if (tid < B*K){
        int b = tid / K; int n = sel[tid];
        size_t idx = (size_t)(b*Co + co)*N + n;
        float a = gC00()[idx]*f2, o = gC01()[idx]*f2, c = gC11()[idx]*f2;
        float det = a*c - o*o;
        ab = fabsf(gW()[idx])*TWO_PI_F*sqrtf(fmaxf(det, 1e-12f));
    }
    red[tid] = ab; __syncthreads();
    for (int s = BLOCK>>1; s; s >>= 1){ if (tid < s) red[tid] += red[tid+s]; __syncthreads(); }
    if (tid == 0) sWS = red[0]/(float)(B*K) + 1e-6f;
    __syncthreads();
    float ws = sWS;

    if (tid < B*K){
        int b = tid / K, t = tid - b*K; int n = sel[tid];
        size_t idx = (size_t)(b*Co + co)*N + n;
        size_t oi  = (size_t)(b*Co + co)*K + t;
        gA(0)[oi] = gW()[idx]/ws;
        gA(1)[oi] = gP0()[idx]*f;   gA(2)[oi] = gP1()[idx]*f;
        gA(3)[oi] = gC00()[idx]*f2; gA(4)[oi] = gC01()[idx]*f2; gA(5)[oi] = gC11()[idx]*f2;
    }
}

// ---------------------------------------------------------------------------
// Layer2 tail: relu_fit finalize + channel norms + integrate. Block per class.
// ---------------------------------------------------------------------------
template<int Co, int N, int CH>
__global__ void __launch_bounds__(256) norm2int_kernel()
{
    constexpr int B = 8, BLOCK = 256;
    int co = blockIdx.x, tid = threadIdx.x;
    __shared__ float red[BLOCK];
    __shared__ float sF, sXb[B], sWS;

    float tr = 0.f;
    for (int e = tid; e < B*N; e += BLOCK){
        int b = e / N, n = e - b*N;
        size_t idx = (size_t)(b*Co + co)*N + n;
        tr += 0.5f*(gC00()[idx] + gC11()[idx]);
    }
    red[tid] = tr; __syncthreads();
    for (int s = BLOCK>>1; s; s >>= 1){ if (tid < s) red[tid] += red[tid+s]; __syncthreads(); }
    if (tid == 0) sF = rsqrtf(red[0]/(float)(B*N) + 1e-8f);
    __syncthreads();
    float f2 = sF*sF;

    float ab = 0.f;
    for (int b = 0; b < B; b++){
        float sb = 0.f;
        for (int n = tid; n < N; n += BLOCK){
            size_t idx = (size_t)(b*Co + co)*N + n;
            float s = 0.f;
            #pragma unroll
            for (int c = 0; c < CH; c++) s += gAcc(c)[idx];
            float w = gW()[idx];
            float denom = (fabsf(s) > 1e-6f) ? s : 1e-6f;
            float wn = w * (fmaxf(s, 0.f)/denom);
            float a = gC00()[idx]*f2, o = gC01()[idx]*f2, c = gC11()[idx]*f2;
            float det = a*c - o*o;
            float iv = wn*TWO_PI_F*sqrtf(fmaxf(det, 1e-12f));
            sb += iv; ab += fabsf(iv);
        }
        red[tid] = sb; __syncthreads();
        for (int s = BLOCK>>1; s; s >>= 1){ if (tid < s) red[tid] += red[tid+s]; __syncthreads(); }
        if (tid == 0) sXb[b] = red[0];
        __syncthreads();
    }
    red[tid] = ab; __syncthreads();
    for (int s = BLOCK>>1; s; s >>= 1){ if (tid < s) red[tid] += red[tid+s]; __syncthreads(); }
    if (tid == 0) sWS = red[0]/(float)(B*N) + 1e-6f;
    __syncthreads();
    if (tid < B) gX()[tid*10 + co] = sXb[tid]/sWS;
}

// ---------------------------------------------------------------------------
// Final BatchNorm1d (training mode) over batch + log_softmax over classes.
// ---------------------------------------------------------------------------
__global__ void final_kernel(float* __restrict__ out)
{
    __shared__ float sx[80], sn2[80];
    int t = threadIdx.x;
    if (t < 80) sx[t] = gX()[t];
    __syncthreads();
    if (t < 10){
        float mu = 0.f;
        for (int b = 0; b < 8; b++) mu += sx[b*10+t];
        mu *= 0.125f;
        float var = 0.f;
        for (int b = 0; b < 8; b++){ float d = sx[b*10+t] - mu; var += d*d; }
        var *= 0.125f;
        float iv = rsqrtf(var + 1e-5f);
        for (int b = 0; b < 8; b++) sn2[b*10+t] = (sx[b*10+t] - mu)*iv;
    }
    __syncthreads();
    if (t < 8){
        float mx = -1e30f;
        for (int c = 0; c < 10; c++) mx = fmaxf(mx, sn2[t*10+c]);
        float se = 0.f;
        for (int c = 0; c < 10; c++) se += expf(sn2[t*10+c] - mx);
        float lse = mx + logf(se);
        for (int c = 0; c < 10; c++) out[t*10+c] = sn2[t*10+c] - lse;
    }
}

// ---------------------------------------------------------------------------
extern "C" void kernel_launch(void* const* d_in, const int* in_sizes, int n_in,
                              void* d_out, int out_size)
{
    const float* in_w = (const float*)d_in[0];
    const float* in_p = (const float*)d_in[1];
    const float* in_c = (const float*)d_in[2];
    const float* k0w  = (const float*)d_in[3];
    const float* k0p  = (const float*)d_in[4];
    const float* k0c  = (const float*)d_in[5];
    const float* k1w  = (const float*)d_in[6];
    const float* k1p  = (const float*)d_in[7];
    const float* k1c  = (const float*)d_in[8];
    const float* k2w  = (const float*)d_in[9];
    const float* k2p  = (const float*)d_in[10];
    const float* k2c  = (const float*)d_in[11];
    float* out = (float*)d_out;

    norm0_kernel<<<8, 128>>>(in_w, in_p, in_c);

    // layer 0: Ci=1,Nd=128,Co=8,Nk=5 -> N=640, n_fit=32, 2 j-chunks
    eval_fused_kernel<1,128,8,5, 640,2,128,5><<<64*2, 128>>>(k0w, k0p, k0c);
    topknorm_kernel<8,640,32,2><<<8, 256>>>();

    // layer 1: Ci=8,Nd=32,Co=16,Nk=5 -> N=1280, n_fit=16, 2 j-chunks
    eval_fused_kernel<8,32,16,5, 1280,2,256,5><<<128*2, 256>>>(k1w, k1p, k1c);
    topknorm_kernel<16,1280,16,2><<<16, 256>>>();

    // layer 2: Ci=16,Nd=16,Co=10,Nk=5 -> N=1280, keep all, 4 j-chunks
    eval_fused_kernel<16,16,10,5, 1280,4,256,5><<<80*4, 256>>>(k2w, k2p, k2c);
    norm2int_kernel<10,1280,4><<<10, 256>>>();

    final_kernel<<<1, 128>>>(out);
}

// round 5
// speedup vs baseline: 1.6743x; 1.2972x over previous
#include <cuda_runtime.h>
#include <math.h>

#define TWO_PI_F 6.283185307179586f
#define L2E_F    1.4426950408889634f

// ---------------------------------------------------------------------------
// Scratch (single __device__ array):
//   gW,gP0,gP1,gC00,gC01,gC11 : per-pair conv components, stride NBUF
//   gAcc[5]                   : slotted eval partial sums (deterministic)
//   gA[6]                     : layer-data set (post-topk / normalized)
//   gX                        : integrated class scores [8*10]
// ---------------------------------------------------------------------------
constexpr int NBUF = 163840;   // max pairs*N = 128*1280 (layer1)
constexpr int NA   = 2048;     // max B*Co*K

__device__ float g_scratch[(size_t)11*NBUF + 6*NA + 128];

__device__ __forceinline__ float* gW()        { return g_scratch + 0*(size_t)NBUF; }
__device__ __forceinline__ float* gP0()       { return g_scratch + 1*(size_t)NBUF; }
__device__ __forceinline__ float* gP1()       { return g_scratch + 2*(size_t)NBUF; }
__device__ __forceinline__ float* gC00()      { return g_scratch + 3*(size_t)NBUF; }
__device__ __forceinline__ float* gC01()      { return g_scratch + 4*(size_t)NBUF; }
__device__ __forceinline__ float* gC11()      { return g_scratch + 5*(size_t)NBUF; }
__device__ __forceinline__ float* gAcc(int c) { return g_scratch + (size_t)(6+c)*NBUF; }
__device__ __forceinline__ float* gA(int k)   { return g_scratch + 11*(size_t)NBUF + (size_t)k*NA; }
__device__ __forceinline__ float* gX()        { return g_scratch + 11*(size_t)NBUF + 6*(size_t)NA; }

__device__ __forceinline__ float ex2f(float x){
    float r; asm("ex2.approx.ftz.f32 %0, %1;" : "=f"(r) : "f"(x)); return r;
}

// ---------------------------------------------------------------------------
// norm0: per-sample CovScaleNorm + WeightNorm on input GM (L=1, N=128)
// ---------------------------------------------------------------------------
__global__ void norm0_kernel(const float* __restrict__ in_w,
                             const float* __restrict__ in_p,
                             const float* __restrict__ in_c)
{
    const int N = 128;
    int b = blockIdx.x, t = threadIdx.x;
    int gi = b*N + t;
    float w  = in_w[gi];
    float px = in_p[gi*2+0], py = in_p[gi*2+1];
    float a  = in_c[gi*4+0], o = in_c[gi*4+1], c = in_c[gi*4+3];

    __shared__ float red[128];
    __shared__ float sval;

    red[t] = 0.5f*(a + c); __syncthreads();
    for (int s = N/2; s > 0; s >>= 1){ if (t < s) red[t] += red[t+s]; __syncthreads(); }
    if (t == 0) sval = rsqrtf(red[0]/(float)N + 1e-8f);
    __syncthreads();
    float f = sval, f2 = f*f;
    px *= f; py *= f; a *= f2; o *= f2; c *= f2;

    float det = a*c - o*o;
    float iv  = fabsf(w)*TWO_PI_F*sqrtf(fmaxf(det, 1e-12f));
    __syncthreads();
    red[t] = iv; __syncthreads();
    for (int s = N/2; s > 0; s >>= 1){ if (t < s) red[t] += red[t+s]; __syncthreads(); }
    if (t == 0) sval = red[0]/(float)N + 1e-6f;
    __syncthreads();
    w /= sval;

    gA(0)[gi]=w;  gA(1)[gi]=px; gA(2)[gi]=py;
    gA(3)[gi]=a;  gA(4)[gi]=o;  gA(5)[gi]=c;
}

// ---------------------------------------------------------------------------
// Fused conv + eval-at-centers, chunked over j. One block per (pair, chunk).
// Per-j record: monomial coefficients of the quadratic form, log2(e) folded,
// log2|w| folded into the constant K, sign kept separate.
//   q(x,y) = A*x^2 + B*x*y + C*y^2 + L1*x + L2*y + K
//   contribution = sgn * 2^q
// Inner body: 5 FFMA + 1 EX2 + 1 FFMA per eval (MUFU-bound ~8 cyc/warp-eval).
// ---------------------------------------------------------------------------
template<int Ci, int Nd, int Co, int Nk, int N, int CH, int BLOCK, int IPT>
__global__ void __launch_bounds__(BLOCK) eval_fused_kernel(
    const float* __restrict__ kw, const float* __restrict__ kp,
    const float* __restrict__ kc)
{
    static_assert(N == BLOCK*IPT, "i tiling");
    static_assert(N % CH == 0, "j chunking");
    constexpr int NJ = N / CH;
    int pair  = blockIdx.x / CH;
    int chunk = blockIdx.x - pair*CH;
    int b  = pair / Co;
    int co = pair - b*Co;
    size_t base = (size_t)pair * N;

    __shared__ float4 sJ1[NJ];   // (A, B, C, K)
    __shared__ float4 sJ2[NJ];   // (L1, L2, sgn, 0)

    const float* Aw  = gA(0); const float* Ap0 = gA(1); const float* Ap1 = gA(2);
    const float* Ac00= gA(3); const float* Ac01= gA(4); const float* Ac11= gA(5);

    for (int jj = threadIdx.x; jj < NJ; jj += BLOCK){
        int n  = chunk*NJ + jj;
        int nk = n % Nk;  int t2 = n / Nk;
        int nd = t2 % Nd; int ci = t2 / Nd;
        int di = (b*Ci + ci)*Nd + nd;
        int ki = (co*Ci + ci)*Nk + nk;

        float d00=Ac00[di], d01=Ac01[di], d11=Ac11[di];
        float k00=kc[ki*4+0], k01=kc[ki*4+1], k11=kc[ki*4+3];
        float s00=d00+k00, s01=d01+k01, s11=d11+k11;

        float det_d = d00*d11 - d01*d01;
        float det_k = k00*k11 - k01*k01;
        float det_s = s00*s11 - s01*s01;
        float amp = TWO_PI_F * sqrtf(fmaxf(det_d*det_k/fmaxf(det_s,1e-12f), 1e-20f));
        float wv  = Aw[di]*kw[ki]*amp;
        float px  = Ap0[di] + kp[ki*2+0];
        float py  = Ap1[di] + kp[ki*2+1];
        float inv = 1.0f/det_s;

        // log2e-scaled -0.5*P
        float A = -0.5f*s11*inv*L2E_F;
        float Bc =  s01*inv*L2E_F;
        float Cc = -0.5f*s00*inv*L2E_F;
        float l1 = -(2.f*A*px + Bc*py);
        float l2 = -(Bc*px + 2.f*Cc*py);
        float K  = A*px*px + Bc*px*py + Cc*py*py + __log2f(fabsf(wv));
        float sg = copysignf(1.f, wv);

        sJ1[jj] = make_float4(A, Bc, Cc, K);
        sJ2[jj] = make_float4(l1, l2, sg, 0.f);

        gW()  [base+n] = wv;
        gP0() [base+n] = px;  gP1() [base+n] = py;
        gC00()[base+n] = s00; gC01()[base+n] = s01; gC11()[base+n] = s11;
    }
    __syncthreads();

    float acc[IPT], vx[IPT], vy[IPT], vxx[IPT], vxy[IPT], vyy[IPT];
    #pragma unroll
    for (int k = 0; k < IPT; k++){
        int i  = threadIdx.x + k*BLOCK;
        int nk = i % Nk;  int t2 = i / Nk;
        int nd = t2 % Nd; int ci = t2 / Nd;
        int di = (b*Ci + ci)*Nd + nd;
        int ki = (co*Ci + ci)*Nk + nk;
        float x = Ap0[di] + kp[ki*2+0];
        float y = Ap1[di] + kp[ki*2+1];
        vx[k]=x; vy[k]=y; vxx[k]=x*x; vxy[k]=x*y; vyy[k]=y*y;
        acc[k] = 0.f;
    }

    #pragma unroll 2
    for (int jj = 0; jj < NJ; jj++){
        float4 j1 = sJ1[jj];
        float4 j2 = sJ2[jj];
        #pragma unroll
        for (int k = 0; k < IPT; k++){
            float q = fmaf(j2.y, vy[k], j1.w);
            q = fmaf(j2.x, vx[k],  q);
            q = fmaf(j1.z, vyy[k], q);
            q = fmaf(j1.y, vxy[k], q);
            q = fmaf(j1.x, vxx[k], q);
            acc[k] = fmaf(j2.z, ex2f(q), acc[k]);
        }
    }

    float* out = gAcc(chunk);
    #pragma unroll
    for (int k = 0; k < IPT; k++)
        out[base + threadIdx.x + k*BLOCK] = acc[k];
}

// ---------------------------------------------------------------------------
// Fused: relu_fit finalize + top-k (warp per batch, no block barriers in the
// K loop) + channel-wise CovScaleNorm + WeightBatchNorm. Block per co.
// ---------------------------------------------------------------------------
template<int Co, int N, int K, int CH>
__global__ void __launch_bounds__(256) topknorm_kernel()
{
    constexpr int B = 8, BLOCK = 256;
    int co = blockIdx.x, tid = threadIdx.x;

    __shared__ float sSc[B*N];
    __shared__ int   sel[B*K];
    __shared__ float red[BLOCK];
    __shared__ float sF, sWS;

    // finalize s -> w_new, score
    for (int e = tid; e < B*N; e += BLOCK){
        int b = e / N, n = e - b*N;
        size_t idx = (size_t)(b*Co + co)*N + n;
        float s = 0.f;
        #pragma unroll
        for (int c = 0; c < CH; c++) s += gAcc(c)[idx];
        float w = gW()[idx];
        float denom = (fabsf(s) > 1e-6f) ? s : 1e-6f;
        float wn = w * (fmaxf(s, 0.f)/denom);
        gW()[idx] = wn;
        float c00 = gC00()[idx], c01 = gC01()[idx], c11 = gC11()[idx];
        float det = c00*c11 - c01*c01;
        sSc[e] = fabsf(wn)*sqrtf(fmaxf(det, 1e-12f));
    }
    __syncthreads();

    // top-k: warp wid handles batch b=wid (scores >= 0; -2 marks consumed)
    int lane = tid & 31, wid = tid >> 5;
    float* sc = sSc + wid*N;
    for (int it = 0; it < K; it++){
        float bv = -1.f; int bi = 1 << 30;
        for (int j = lane; j < N; j += 32){
            float v = sc[j];
            if (v > bv || (v == bv && j < bi)){ bv = v; bi = j; }
        }
        #pragma unroll
        for (int off = 16; off; off >>= 1){
            float ov = __shfl_down_sync(0xffffffffu, bv, off);
            int   oi = __shfl_down_sync(0xffffffffu, bi, off);
            if (ov > bv || (ov == bv && oi < bi)){ bv = ov; bi = oi; }
        }
        if (lane == 0){ sel[wid*K + it] = bi; sc[bi] = -2.f; }
        __syncwarp();
    }
    __syncthreads();

    // cov-scale stats over selected (B*K <= 256)
    float tr = 0.f;
    if (tid < B*K){
        int b = tid / K; int n = sel[tid];
        size_t idx = (size_t)(b*Co + co)*N + n;
        tr = 0.5f*(gC00()[idx] + gC11()[idx]);
    }
    red[tid] = tr; __syncthreads();
    for (int s = BLOCK>>1; s; s >>= 1){ if (tid < s) red[tid] += red[tid+s]; __syncthreads(); }
    if (tid == 0) sF = rsqrtf(red[0]/(float)(B*K) + 1e-8f);
    __syncthreads();
    float f = sF, f2 = f*f;

    // weight-norm scale with SCALED covariances
    float ab = 0.f;
    if (tid < B*K){
        int b = tid / K; int n = sel[tid];
        size_t idx = (size_t)(b*Co + co)*N + n;
        float a = gC00()[idx]*f2, o = gC01()[idx]*f2, c = gC11()[idx]*f2;
        float det = a*c - o*o;
        ab = fabsf(gW()[idx])*TWO_PI_F*sqrtf(fmaxf(det, 1e-12f));
    }
    red[tid] = ab; __syncthreads();
    for (int s = BLOCK>>1; s; s >>= 1){ if (tid < s) red[tid] += red[tid+s]; __syncthreads(); }
    if (tid == 0) sWS = red[0]/(float)(B*K) + 1e-6f;
    __syncthreads();
    float ws = sWS;

    if (tid < B*K){
        int b = tid / K, t = tid - b*K; int n = sel[tid];
        size_t idx = (size_t)(b*Co + co)*N + n;
        size_t oi  = (size_t)(b*Co + co)*K + t;
        gA(0)[oi] = gW()[idx]/ws;
        gA(1)[oi] = gP0()[idx]*f;   gA(2)[oi] = gP1()[idx]*f;
        gA(3)[oi] = gC00()[idx]*f2; gA(4)[oi] = gC01()[idx]*f2; gA(5)[oi] = gC11()[idx]*f2;
    }
}

// ---------------------------------------------------------------------------
// Layer2 tail: relu_fit finalize + channel norms + integrate. Block per class,
// warp per batch (shuffle reductions, minimal barriers).
// ---------------------------------------------------------------------------
template<int Co, int N, int CH>
__global__ void __launch_bounds__(256) norm2int_kernel()
{
    constexpr int B = 8, BLOCK = 256;
    int co = blockIdx.x, tid = threadIdx.x;
    int lane = tid & 31, wid = tid >> 5;
    __shared__ float red[BLOCK];
    __shared__ float sF, sXb[B], sAb[B];

    // mean covariance trace over all (b, n)
    float tr = 0.f;
    for (int e = tid; e < B*N; e += BLOCK){
        int b = e / N, n = e - b*N;
        size_t idx = (size_t)(b*Co + co)*N + n;
        tr += 0.5f*(gC00()[idx] + gC11()[idx]);
    }
    red[tid] = tr; __syncthreads();
    for (int s = BLOCK>>1; s; s >>= 1){ if (tid < s) red[tid] += red[tid+s]; __syncthreads(); }
    if (tid == 0) sF = rsqrtf(red[0]/(float)(B*N) + 1e-8f);
    __syncthreads();
    float f2 = sF*sF;

    // warp wid handles batch b=wid: finalize + integrate
    {
        int b = wid;
        float sb = 0.f, ab = 0.f;
        for (int n = lane; n < N; n += 32){
            size_t idx = (size_t)(b*Co + co)*N + n;
            float s = 0.f;
            #pragma unroll
            for (int c = 0; c < CH; c++) s += gAcc(c)[idx];
            float w = gW()[idx];
            float denom = (fabsf(s) > 1e-6f) ? s : 1e-6f;
            float wn = w * (fmaxf(s, 0.f)/denom);
            float a = gC00()[idx]*f2, o = gC01()[idx]*f2, c = gC11()[idx]*f2;
            float det = a*c - o*o;
            float iv = wn*TWO_PI_F*sqrtf(fmaxf(det, 1e-12f));
            sb += iv; ab += fabsf(iv);
        }
        #pragma unroll
        for (int off = 16; off; off >>= 1){
            sb += __shfl_down_sync(0xffffffffu, sb, off);
            ab += __shfl_down_sync(0xffffffffu, ab, off);
        }
        if (lane == 0){ sXb[b] = sb; sAb[b] = ab; }
    }
    __syncthreads();
    if (tid < B){
        float ws = (sAb[0]+sAb[1]+sAb[2]+sAb[3]+sAb[4]+sAb[5]+sAb[6]+sAb[7])
                   /(float)(B*N) + 1e-6f;
        gX()[tid*10 + co] = sXb[tid]/ws;
    }
}

// ---------------------------------------------------------------------------
// Final BatchNorm1d (training mode) over batch + log_softmax over classes.
// ---------------------------------------------------------------------------
__global__ void final_kernel(float* __restrict__ out)
{
    __shared__ float sx[80], sn2[80];
    int t = threadIdx.x;
    if (t < 80) sx[t] = gX()[t];
    __syncthreads();
    if (t < 10){
        float mu = 0.f;
        for (int b = 0; b < 8; b++) mu += sx[b*10+t];
        mu *= 0.125f;
        float var = 0.f;
        for (int b = 0; b < 8; b++){ float d = sx[b*10+t] - mu; var += d*d; }
        var *= 0.125f;
        float iv = rsqrtf(var + 1e-5f);
        for (int b = 0; b < 8; b++) sn2[b*10+t] = (sx[b*10+t] - mu)*iv;
    }
    __syncthreads();
    if (t < 8){
        float mx = -1e30f;
        for (int c = 0; c < 10; c++) mx = fmaxf(mx, sn2[t*10+c]);
        float se = 0.f;
        for (int c = 0; c < 10; c++) se += expf(sn2[t*10+c] - mx);
        float lse = mx + logf(se);
        for (int c = 0; c < 10; c++) out[t*10+c] = sn2[t*10+c] - lse;
    }
}

// ---------------------------------------------------------------------------
extern "C" void kernel_launch(void* const* d_in, const int* in_sizes, int n_in,
                              void* d_out, int out_size)
{
    const float* in_w = (const float*)d_in[0];
    const float* in_p = (const float*)d_in[1];
    const float* in_c = (const float*)d_in[2];
    const float* k0w  = (const float*)d_in[3];
    const float* k0p  = (const float*)d_in[4];
    const float* k0c  = (const float*)d_in[5];
    const float* k1w  = (const float*)d_in[6];
    const float* k1p  = (const float*)d_in[7];
    const float* k1c  = (const float*)d_in[8];
    const float* k2w  = (const float*)d_in[9];
    const float* k2p  = (const float*)d_in[10];
    const float* k2c  = (const float*)d_in[11];
    float* out = (float*)d_out;

    norm0_kernel<<<8, 128>>>(in_w, in_p, in_c);

    // layer 0: Ci=1,Nd=128,Co=8,Nk=5 -> N=640, n_fit=32, 4 j-chunks
    eval_fused_kernel<1,128,8,5, 640,4,128,5><<<64*4, 128>>>(k0w, k0p, k0c);
    topknorm_kernel<8,640,32,4><<<8, 256>>>();

    // layer 1: Ci=8,Nd=32,Co=16,Nk=5 -> N=1280, n_fit=16, 4 j-chunks
    eval_fused_kernel<8,32,16,5, 1280,4,256,5><<<128*4, 256>>>(k1w, k1p, k1c);
    topknorm_kernel<16,1280,16,4><<<16, 256>>>();

    // layer 2: Ci=16,Nd=16,Co=10,Nk=5 -> N=1280, keep all, 5 j-chunks
    eval_fused_kernel<16,16,10,5, 1280,5,256,5><<<80*5, 256>>>(k2w, k2p, k2c);
    norm2int_kernel<10,1280,5><<<10, 256>>>();

    final_kernel<<<1, 128>>>(out);
}

// round 7
// speedup vs baseline: 1.7883x; 1.0681x over previous
#include <cuda_runtime.h>
#include <math.h>

#define TWO_PI_F 6.283185307179586f
#define L2E_F    1.4426950408889634f

typedef unsigned long long ull;

// ---------------------------------------------------------------------------
// Scratch (single __device__ array)
// ---------------------------------------------------------------------------
constexpr int NBUF = 163840;   // max pairs*N = 128*1280 (layer1)
constexpr int NA   = 2048;     // max B*Co*K

__device__ float g_scratch[(size_t)14*NBUF + 6*NA + 128];

__device__ __forceinline__ float* gW()        { return g_scratch + 0*(size_t)NBUF; }
__device__ __forceinline__ float* gP0()       { return g_scratch + 1*(size_t)NBUF; }
__device__ __forceinline__ float* gP1()       { return g_scratch + 2*(size_t)NBUF; }
__device__ __forceinline__ float* gC00()      { return g_scratch + 3*(size_t)NBUF; }
__device__ __forceinline__ float* gC01()      { return g_scratch + 4*(size_t)NBUF; }
__device__ __forceinline__ float* gC11()      { return g_scratch + 5*(size_t)NBUF; }
__device__ __forceinline__ float* gAcc(int c) { return g_scratch + (size_t)(6+c)*NBUF; }
__device__ __forceinline__ float* gA(int k)   { return g_scratch + 14*(size_t)NBUF + (size_t)k*NA; }
__device__ __forceinline__ float* gX()        { return g_scratch + 14*(size_t)NBUF + 6*(size_t)NA; }

__device__ __forceinline__ float ex2f(float x){
    float r; asm("ex2.approx.ftz.f32 %0, %1;" : "=f"(r) : "f"(x)); return r;
}
__device__ __forceinline__ ull pk2(float lo, float hi){
    ull r; asm("mov.b64 %0, {%1, %2};" : "=l"(r) : "f"(lo), "f"(hi)); return r;
}
__device__ __forceinline__ void upk2(float& lo, float& hi, ull v){
    asm("mov.b64 {%0, %1}, %2;" : "=f"(lo), "=f"(hi) : "l"(v));
}
__device__ __forceinline__ ull ffma2(ull a, ull b, ull c){
    ull d; asm("fma.rn.f32x2 %0, %1, %2, %3;" : "=l"(d) : "l"(a), "l"(b), "l"(c)); return d;
}

// ---------------------------------------------------------------------------
// norm0: per-sample CovScaleNorm + WeightNorm on input GM (L=1, N=128)
// ---------------------------------------------------------------------------
__global__ void norm0_kernel(const float* __restrict__ in_w,
                             const float* __restrict__ in_p,
                             const float* __restrict__ in_c)
{
    const int N = 128;
    int b = blockIdx.x, t = threadIdx.x;
    int gi = b*N + t;
    float w  = in_w[gi];
    float px = in_p[gi*2+0], py = in_p[gi*2+1];
    float a  = in_c[gi*4+0], o = in_c[gi*4+1], c = in_c[gi*4+3];

    __shared__ float red[128];
    __shared__ float sval;

    red[t] = 0.5f*(a + c); __syncthreads();
    for (int s = N/2; s > 0; s >>= 1){ if (t < s) red[t] += red[t+s]; __syncthreads(); }
    if (t == 0) sval = rsqrtf(red[0]/(float)N + 1e-8f);
    __syncthreads();
    float f = sval, f2 = f*f;
    px *= f; py *= f; a *= f2; o *= f2; c *= f2;

    float det = a*c - o*o;
    float iv  = fabsf(w)*TWO_PI_F*sqrtf(fmaxf(det, 1e-12f));
    __syncthreads();
    red[t] = iv; __syncthreads();
    for (int s = N/2; s > 0; s >>= 1){ if (t < s) red[t] += red[t+s]; __syncthreads(); }
    if (t == 0) sval = red[0]/(float)N + 1e-6f;
    __syncthreads();
    w /= sval;

    gA(0)[gi]=w;  gA(1)[gi]=px; gA(2)[gi]=py;
    gA(3)[gi]=a;  gA(4)[gi]=o;  gA(5)[gi]=c;
}

// ---------------------------------------------------------------------------
// Fused conv + eval-at-centers, chunked over j, packed f32x2 math.
//   q(x,y) = A*x^2 + B*x*y + C*y^2 + L1*x + L2*y + K  (log2e, log2|w| folded)
//   contribution = sgn * 2^q
// Two i's per f32x2 lane pair: 5 FFMA2 + unpack + 2 EX2 + pack + FFMA2.
// ---------------------------------------------------------------------------
template<int Ci, int Nd, int Co, int Nk, int N, int CH, int BLOCK, int IPT>
__global__ void __launch_bounds__(BLOCK) eval_fused_kernel(
    const float* __restrict__ kw, const float* __restrict__ kp,
    const float* __restrict__ kc)
{
    static_assert(N == BLOCK*IPT, "i tiling");
    static_assert(N % CH == 0, "j chunking");
    static_assert(IPT % 2 == 0, "pairing");
    constexpr int NJ = N / CH;
    constexpr int NP = IPT/2;
    int pair  = blockIdx.x / CH;
    int chunk = blockIdx.x - pair*CH;
    int b  = pair / Co;
    int co = pair - b*Co;
    size_t base = (size_t)pair * N;

    __shared__ float4 sJ1[NJ];   // (A, B, C, K)
    __shared__ float4 sJ2[NJ];   // (L1, L2, sgn, 0)

    const float* Aw  = gA(0); const float* Ap0 = gA(1); const float* Ap1 = gA(2);
    const float* Ac00= gA(3); const float* Ac01= gA(4); const float* Ac11= gA(5);

    for (int jj = threadIdx.x; jj < NJ; jj += BLOCK){
        int n  = chunk*NJ + jj;
        int nk = n % Nk;  int t2 = n / Nk;
        int nd = t2 % Nd; int ci = t2 / Nd;
        int di = (b*Ci + ci)*Nd + nd;
        int ki = (co*Ci + ci)*Nk + nk;

        float d00=Ac00[di], d01=Ac01[di], d11=Ac11[di];
        float k00=kc[ki*4+0], k01=kc[ki*4+1], k11=kc[ki*4+3];
        float s00=d00+k00, s01=d01+k01, s11=d11+k11;

        float det_d = d00*d11 - d01*d01;
        float det_k = k00*k11 - k01*k01;
        float det_s = s00*s11 - s01*s01;
        float amp = TWO_PI_F * sqrtf(fmaxf(det_d*det_k/fmaxf(det_s,1e-12f), 1e-20f));
        float wv  = Aw[di]*kw[ki]*amp;
        float px  = Ap0[di] + kp[ki*2+0];
        float py  = Ap1[di] + kp[ki*2+1];
        float inv = 1.0f/det_s;

        float A = -0.5f*s11*inv*L2E_F;
        float Bc =  s01*inv*L2E_F;
        float Cc = -0.5f*s00*inv*L2E_F;
        float l1 = -(2.f*A*px + Bc*py);
        float l2 = -(Bc*px + 2.f*Cc*py);
        float K  = A*px*px + Bc*px*py + Cc*py*py + __log2f(fabsf(wv));
        float sg = copysignf(1.f, wv);

        sJ1[jj] = make_float4(A, Bc, Cc, K);
        sJ2[jj] = make_float4(l1, l2, sg, 0.f);

        gW()  [base+n] = wv;
        gP0() [base+n] = px;  gP1() [base+n] = py;
        gC00()[base+n] = s00; gC01()[base+n] = s01; gC11()[base+n] = s11;
    }
    __syncthreads();

    ull acc2[NP], vx2[NP], vy2[NP], vxx2[NP], vxy2[NP], vyy2[NP];
    #pragma unroll
    for (int p = 0; p < NP; p++){
        float x[2], y[2];
        #pragma unroll
        for (int h = 0; h < 2; h++){
            int i  = threadIdx.x + (2*p+h)*BLOCK;
            int nk = i % Nk;  int t2 = i / Nk;
            int nd = t2 % Nd; int ci = t2 / Nd;
            int di = (b*Ci + ci)*Nd + nd;
            int ki = (co*Ci + ci)*Nk + nk;
            x[h] = Ap0[di] + kp[ki*2+0];
            y[h] = Ap1[di] + kp[ki*2+1];
        }
        vx2 [p] = pk2(x[0],      x[1]);
        vy2 [p] = pk2(y[0],      y[1]);
        vxx2[p] = pk2(x[0]*x[0], x[1]*x[1]);
        vxy2[p] = pk2(x[0]*y[0], x[1]*y[1]);
        vyy2[p] = pk2(y[0]*y[0], y[1]*y[1]);
        acc2[p] = pk2(0.f, 0.f);
    }

    #pragma unroll 2
    for (int jj = 0; jj < NJ; jj++){
        float4 j1 = sJ1[jj];
        float4 j2 = sJ2[jj];
        ull A2  = pk2(j1.x, j1.x), B2  = pk2(j1.y, j1.y);
        ull C2  = pk2(j1.z, j1.z), K2  = pk2(j1.w, j1.w);
        ull L1v = pk2(j2.x, j2.x), L2v = pk2(j2.y, j2.y);
        ull S2  = pk2(j2.z, j2.z);
        #pragma unroll
        for (int p = 0; p < NP; p++){
            ull q = ffma2(L2v, vy2[p], K2);
            q = ffma2(L1v, vx2 [p], q);
            q = ffma2(C2,  vyy2[p], q);
            q = ffma2(B2,  vxy2[p], q);
            q = ffma2(A2,  vxx2[p], q);
            float ql, qh; upk2(ql, qh, q);
            ull e = pk2(ex2f(ql), ex2f(qh));
            acc2[p] = ffma2(S2, e, acc2[p]);
        }
    }

    float* out = gAcc(chunk);
    #pragma unroll
    for (int p = 0; p < NP; p++){
        float a0, a1; upk2(a0, a1, acc2[p]);
        out[base + threadIdx.x + (2*p+0)*BLOCK] = a0;
        out[base + threadIdx.x + (2*p+1)*BLOCK] = a1;
    }
}

// ---------------------------------------------------------------------------
// Fused: relu_fit finalize + top-k (warp per batch) + channel norms.
// ---------------------------------------------------------------------------
template<int Co, int N, int K, int CH>
__global__ void __launch_bounds__(256) topknorm_kernel()
{
    constexpr int B = 8, BLOCK = 256;
    int co = blockIdx.x, tid = threadIdx.x;

    __shared__ float sSc[B*N];
    __shared__ int   sel[B*K];
    __shared__ float red[BLOCK];
    __shared__ float sF, sWS;

    for (int e = tid; e < B*N; e += BLOCK){
        int b = e / N, n = e - b*N;
        size_t idx = (size_t)(b*Co + co)*N + n;
        float s = 0.f;
        #pragma unroll
        for (int c = 0; c < CH; c++) s += gAcc(c)[idx];
        float w = gW()[idx];
        float denom = (fabsf(s) > 1e-6f) ? s : 1e-6f;
        float wn = w * (fmaxf(s, 0.f)/denom);
        gW()[idx] = wn;
        float c00 = gC00()[idx], c01 = gC01()[idx], c11 = gC11()[idx];
        float det = c00*c11 - c01*c01;
        sSc[e] = fabsf(wn)*sqrtf(fmaxf(det, 1e-12f));
    }
    __syncthreads();

    int lane = tid & 31, wid = tid >> 5;
    float* sc = sSc + wid*N;
    for (int it = 0; it < K; it++){
        float bv = -1.f; int bi = 1 << 30;
        for (int j = lane; j < N; j += 32){
            float v = sc[j];
            if (v > bv || (v == bv && j < bi)){ bv = v; bi = j; }
        }
        #pragma unroll
        for (int off = 16; off; off >>= 1){
            float ov = __shfl_down_sync(0xffffffffu, bv, off);
            int   oi = __shfl_down_sync(0xffffffffu, bi, off);
            if (ov > bv || (ov == bv && oi < bi)){ bv = ov; bi = oi; }
        }
        if (lane == 0){ sel[wid*K + it] = bi; sc[bi] = -2.f; }
        __syncwarp();
    }
    __syncthreads();

    float tr = 0.f;
    if (tid < B*K){
        int b = tid / K; int n = sel[tid];
        size_t idx = (size_t)(b*Co + co)*N + n;
        tr = 0.5f*(gC00()[idx] + gC11()[idx]);
    }
    red[tid] = tr; __syncthreads();
    for (int s = BLOCK>>1; s; s >>= 1){ if (tid < s) red[tid] += red[tid+s]; __syncthreads(); }
    if (tid == 0) sF = rsqrtf(red[0]/(float)(B*K) + 1e-8f);
    __syncthreads();
    float f = sF, f2 = f*f;

    float ab = 0.f;
    if (tid < B*K){
        int b = tid / K; int n = sel[tid];
        size_t idx = (size_t)(b*Co + co)*N + n;
        float a = gC00()[idx]*f2, o = gC01()[idx]*f2, c = gC11()[idx]*f2;
        float det = a*c - o*o;
        ab = fabsf(gW()[idx])*TWO_PI_F*sqrtf(fmaxf(det, 1e-12f));
    }
    red[tid] = ab; __syncthreads();
    for (int s = BLOCK>>1; s; s >>= 1){ if (tid < s) red[tid] += red[tid+s]; __syncthreads(); }
    if (tid == 0) sWS = red[0]/(float)(B*K) + 1e-6f;
    __syncthreads();
    float ws = sWS;

    if (tid < B*K){
        int b = tid / K, t = tid - b*K; int n = sel[tid];
        size_t idx = (size_t)(b*Co + co)*N + n;
        size_t oi  = (size_t)(b*Co + co)*K + t;
        gA(0)[oi] = gW()[idx]/ws;
        gA(1)[oi] = gP0()[idx]*f;   gA(2)[oi] = gP1()[idx]*f;
        gA(3)[oi] = gC00()[idx]*f2; gA(4)[oi] = gC01()[idx]*f2; gA(5)[oi] = gC11()[idx]*f2;
    }
}

// ---------------------------------------------------------------------------
// Layer2 tail: relu_fit finalize + channel norms + integrate.
// ---------------------------------------------------------------------------
template<int Co, int N, int CH>
__global__ void __launch_bounds__(256) norm2int_kernel()
{
    constexpr int B = 8, BLOCK = 256;
    int co = blockIdx.x, tid = threadIdx.x;
    int lane = tid & 31, wid = tid >> 5;
    __shared__ float red[BLOCK];
    __shared__ float sF, sXb[B], sAb[B];

    float tr = 0.f;
    for (int e = tid; e < B*N; e += BLOCK){
        int b = e / N, n = e - b*N;
        size_t idx = (size_t)(b*Co + co)*N + n;
        tr += 0.5f*(gC00()[idx] + gC11()[idx]);
    }
    red[tid] = tr; __syncthreads();
    for (int s = BLOCK>>1; s; s >>= 1){ if (tid < s) red[tid] += red[tid+s]; __syncthreads(); }
    if (tid == 0) sF = rsqrtf(red[0]/(float)(B*N) + 1e-8f);
    __syncthreads();
    float f2 = sF*sF;

    {
        int b = wid;
        float sb = 0.f, ab = 0.f;
        for (int n = lane; n < N; n += 32){
            size_t idx = (size_t)(b*Co + co)*N + n;
            float s = 0.f;
            #pragma unroll
            for (int c = 0; c < CH; c++) s += gAcc(c)[idx];
            float w = gW()[idx];
            float denom = (fabsf(s) > 1e-6f) ? s : 1e-6f;
            float wn = w * (fmaxf(s, 0.f)/denom);
            float a = gC00()[idx]*f2, o = gC01()[idx]*f2, c = gC11()[idx]*f2;
            float det = a*c - o*o;
            float iv = wn*TWO_PI_F*sqrtf(fmaxf(det, 1e-12f));
            sb += iv; ab += fabsf(iv);
        }
        #pragma unroll
        for (int off = 16; off; off >>= 1){
            sb += __shfl_down_sync(0xffffffffu, sb, off);
            ab += __shfl_down_sync(0xffffffffu, ab, off);
        }
        if (lane == 0){ sXb[b] = sb; sAb[b] = ab; }
    }
    __syncthreads();
    if (tid < B){
        float ws = (sAb[0]+sAb[1]+sAb[2]+sAb[3]+sAb[4]+sAb[5]+sAb[6]+sAb[7])
                   /(float)(B*N) + 1e-6f;
        gX()[tid*10 + co] = sXb[tid]/ws;
    }
}

// ---------------------------------------------------------------------------
// Final BatchNorm1d + log_softmax.
// ---------------------------------------------------------------------------
__global__ void final_kernel(float* __restrict__ out)
{
    __shared__ float sx[80], sn2[80];
    int t = threadIdx.x;
    if (t < 80) sx[t] = gX()[t];
    __syncthreads();
    if (t < 10){
        float mu = 0.f;
        for (int b = 0; b < 8; b++) mu += sx[b*10+t];
        mu *= 0.125f;
        float var = 0.f;
        for (int b = 0; b < 8; b++){ float d = sx[b*10+t] - mu; var += d*d; }
        var *= 0.125f;
        float iv = rsqrtf(var + 1e-5f);
        for (int b = 0; b < 8; b++) sn2[b*10+t] = (sx[b*10+t] - mu)*iv;
    }
    __syncthreads();
    if (t < 8){
        float mx = -1e30f;
        for (int c = 0; c < 10; c++) mx = fmaxf(mx, sn2[t*10+c]);
        float se = 0.f;
        for (int c = 0; c < 10; c++) se += expf(sn2[t*10+c] - mx);
        float lse = mx + logf(se);
        for (int c = 0; c < 10; c++) out[t*10+c] = sn2[t*10+c] - lse;
    }
}

// ---------------------------------------------------------------------------
extern "C" void kernel_launch(void* const* d_in, const int* in_sizes, int n_in,
                              void* d_out, int out_size)
{
    const float* in_w = (const float*)d_in[0];
    const float* in_p = (const float*)d_in[1];
    const float* in_c = (const float*)d_in[2];
    const float* k0w  = (const float*)d_in[3];
    const float* k0p  = (const float*)d_in[4];
    const float* k0c  = (const float*)d_in[5];
    const float* k1w  = (const float*)d_in[6];
    const float* k1p  = (const float*)d_in[7];
    const float* k1c  = (const float*)d_in[8];
    const float* k2w  = (const float*)d_in[9];
    const float* k2p  = (const float*)d_in[10];
    const float* k2c  = (const float*)d_in[11];
    float* out = (float*)d_out;

    norm0_kernel<<<8, 128>>>(in_w, in_p, in_c);

    // layer 0: N=640, n_fit=32; BLOCK=64, IPT=10, CH=8 -> grid 512
    eval_fused_kernel<1,128,8,5, 640,8,64,10><<<64*8, 64>>>(k0w, k0p, k0c);
    topknorm_kernel<8,640,32,8><<<8, 256>>>();

    // layer 1: N=1280, n_fit=16; BLOCK=128, IPT=10, CH=5 -> grid 640
    eval_fused_kernel<8,32,16,5, 1280,5,128,10><<<128*5, 128>>>(k1w, k1p, k1c);
    topknorm_kernel<16,1280,16,5><<<16, 256>>>();

    // layer 2: N=1280, keep all; BLOCK=128, IPT=10, CH=5 -> grid 400
    eval_fused_kernel<16,16,10,5, 1280,5,128,10><<<80*5, 128>>>(k2w, k2p, k2c);
    norm2int_kernel<10,1280,5><<<10, 256>>>();

    final_kernel<<<1, 128>>>(out);
}

// round 8
// speedup vs baseline: 2.4668x; 1.3794x over previous
#include <cuda_runtime.h>
#include <math.h>

#define TWO_PI_F 6.283185307179586f
#define L2E_F    1.4426950408889634f

typedef unsigned long long ull;

// ---------------------------------------------------------------------------
// Scratch (single __device__ array)
// ---------------------------------------------------------------------------
constexpr int NBUF = 163840;   // max pairs*N = 128*1280 (layer1)
constexpr int NA   = 2048;     // max B*Co*K

__device__ float g_scratch[(size_t)22*NBUF + 6*NA + 128];

__device__ __forceinline__ float* gW()        { return g_scratch + 0*(size_t)NBUF; }
__device__ __forceinline__ float* gP0()       { return g_scratch + 1*(size_t)NBUF; }
__device__ __forceinline__ float* gP1()       { return g_scratch + 2*(size_t)NBUF; }
__device__ __forceinline__ float* gC00()      { return g_scratch + 3*(size_t)NBUF; }
__device__ __forceinline__ float* gC01()      { return g_scratch + 4*(size_t)NBUF; }
__device__ __forceinline__ float* gC11()      { return g_scratch + 5*(size_t)NBUF; }
__device__ __forceinline__ float* gAcc(int c) { return g_scratch + (size_t)(6+c)*NBUF; }
__device__ __forceinline__ float* gA(int k)   { return g_scratch + 22*(size_t)NBUF + (size_t)k*NA; }
__device__ __forceinline__ float* gX()        { return g_scratch + 22*(size_t)NBUF + 6*(size_t)NA; }

__device__ __forceinline__ float ex2f(float x){
    float r; asm("ex2.approx.ftz.f32 %0, %1;" : "=f"(r) : "f"(x)); return r;
}
__device__ __forceinline__ ull pk2(float lo, float hi){
    ull r; asm("mov.b64 %0, {%1, %2};" : "=l"(r) : "f"(lo), "f"(hi)); return r;
}
__device__ __forceinline__ void upk2(float& lo, float& hi, ull v){
    asm("mov.b64 {%0, %1}, %2;" : "=f"(lo), "=f"(hi) : "l"(v));
}
__device__ __forceinline__ ull ffma2(ull a, ull b, ull c){
    ull d; asm("fma.rn.f32x2 %0, %1, %2, %3;" : "=l"(d) : "l"(a), "l"(b), "l"(c)); return d;
}

// ---------------------------------------------------------------------------
// norm0: per-sample CovScaleNorm + WeightNorm on input GM (L=1, N=128)
// ---------------------------------------------------------------------------
__global__ void norm0_kernel(const float* __restrict__ in_w,
                             const float* __restrict__ in_p,
                             const float* __restrict__ in_c)
{
    const int N = 128;
    int b = blockIdx.x, t = threadIdx.x;
    int gi = b*N + t;
    float w  = in_w[gi];
    float px = in_p[gi*2+0], py = in_p[gi*2+1];
    float a  = in_c[gi*4+0], o = in_c[gi*4+1], c = in_c[gi*4+3];

    __shared__ float red[128];
    __shared__ float sval;

    red[t] = 0.5f*(a + c); __syncthreads();
    for (int s = N/2; s > 0; s >>= 1){ if (t < s) red[t] += red[t+s]; __syncthreads(); }
    if (t == 0) sval = rsqrtf(red[0]/(float)N + 1e-8f);
    __syncthreads();
    float f = sval, f2 = f*f;
    px *= f; py *= f; a *= f2; o *= f2; c *= f2;

    float det = a*c - o*o;
    float iv  = fabsf(w)*TWO_PI_F*sqrtf(fmaxf(det, 1e-12f));
    __syncthreads();
    red[t] = iv; __syncthreads();
    for (int s = N/2; s > 0; s >>= 1){ if (t < s) red[t] += red[t+s]; __syncthreads(); }
    if (t == 0) sval = red[0]/(float)N + 1e-6f;
    __syncthreads();
    w /= sval;

    gA(0)[gi]=w;  gA(1)[gi]=px; gA(2)[gi]=py;
    gA(3)[gi]=a;  gA(4)[gi]=o;  gA(5)[gi]=c;
}

// ---------------------------------------------------------------------------
// Fused conv + eval-at-centers, chunked over j, packed f32x2 math.
//   q(x,y) = A*x^2 + B*x*y + C*y^2 + L1*x + L2*y + K  (log2e, log2|w| folded)
// ---------------------------------------------------------------------------
template<int Ci, int Nd, int Co, int Nk, int N, int CH, int BLOCK, int IPT>
__global__ void __launch_bounds__(BLOCK) eval_fused_kernel(
    const float* __restrict__ kw, const float* __restrict__ kp,
    const float* __restrict__ kc)
{
    static_assert(N == BLOCK*IPT, "i tiling");
    static_assert(N % CH == 0, "j chunking");
    static_assert(IPT % 2 == 0, "pairing");
    constexpr int NJ = N / CH;
    constexpr int NP = IPT/2;
    int pair  = blockIdx.x / CH;
    int chunk = blockIdx.x - pair*CH;
    int b  = pair / Co;
    int co = pair - b*Co;
    size_t base = (size_t)pair * N;

    __shared__ float4 sJ1[NJ];   // (A, B, C, K)
    __shared__ float4 sJ2[NJ];   // (L1, L2, sgn, 0)

    const float* Aw  = gA(0); const float* Ap0 = gA(1); const float* Ap1 = gA(2);
    const float* Ac00= gA(3); const float* Ac01= gA(4); const float* Ac11= gA(5);

    for (int jj = threadIdx.x; jj < NJ; jj += BLOCK){
        int n  = chunk*NJ + jj;
        int nk = n % Nk;  int t2 = n / Nk;
        int nd = t2 % Nd; int ci = t2 / Nd;
        int di = (b*Ci + ci)*Nd + nd;
        int ki = (co*Ci + ci)*Nk + nk;

        float d00=Ac00[di], d01=Ac01[di], d11=Ac11[di];
        float k00=kc[ki*4+0], k01=kc[ki*4+1], k11=kc[ki*4+3];
        float s00=d00+k00, s01=d01+k01, s11=d11+k11;

        float det_d = d00*d11 - d01*d01;
        float det_k = k00*k11 - k01*k01;
        float det_s = s00*s11 - s01*s01;
        float amp = TWO_PI_F * sqrtf(fmaxf(det_d*det_k/fmaxf(det_s,1e-12f), 1e-20f));
        float wv  = Aw[di]*kw[ki]*amp;
        float px  = Ap0[di] + kp[ki*2+0];
        float py  = Ap1[di] + kp[ki*2+1];
        float inv = 1.0f/det_s;

        float A = -0.5f*s11*inv*L2E_F;
        float Bc =  s01*inv*L2E_F;
        float Cc = -0.5f*s00*inv*L2E_F;
        float l1 = -(2.f*A*px + Bc*py);
        float l2 = -(Bc*px + 2.f*Cc*py);
        float K  = A*px*px + Bc*px*py + Cc*py*py + __log2f(fabsf(wv));
        float sg = copysignf(1.f, wv);

        sJ1[jj] = make_float4(A, Bc, Cc, K);
        sJ2[jj] = make_float4(l1, l2, sg, 0.f);

        gW()  [base+n] = wv;
        gP0() [base+n] = px;  gP1() [base+n] = py;
        gC00()[base+n] = s00; gC01()[base+n] = s01; gC11()[base+n] = s11;
    }
    __syncthreads();

    ull acc2[NP], vx2[NP], vy2[NP], vxx2[NP], vxy2[NP], vyy2[NP];
    #pragma unroll
    for (int p = 0; p < NP; p++){
        float x[2], y[2];
        #pragma unroll
        for (int h = 0; h < 2; h++){
            int i  = threadIdx.x + (2*p+h)*BLOCK;
            int nk = i % Nk;  int t2 = i / Nk;
            int nd = t2 % Nd; int ci = t2 / Nd;
            int di = (b*Ci + ci)*Nd + nd;
            int ki = (co*Ci + ci)*Nk + nk;
            x[h] = Ap0[di] + kp[ki*2+0];
            y[h] = Ap1[di] + kp[ki*2+1];
        }
        vx2 [p] = pk2(x[0],      x[1]);
        vy2 [p] = pk2(y[0],      y[1]);
        vxx2[p] = pk2(x[0]*x[0], x[1]*x[1]);
        vxy2[p] = pk2(x[0]*y[0], x[1]*y[1]);
        vyy2[p] = pk2(y[0]*y[0], y[1]*y[1]);
        acc2[p] = pk2(0.f, 0.f);
    }

    #pragma unroll 2
    for (int jj = 0; jj < NJ; jj++){
        float4 j1 = sJ1[jj];
        float4 j2 = sJ2[jj];
        ull A2  = pk2(j1.x, j1.x), B2  = pk2(j1.y, j1.y);
        ull C2  = pk2(j1.z, j1.z), K2  = pk2(j1.w, j1.w);
        ull L1v = pk2(j2.x, j2.x), L2v = pk2(j2.y, j2.y);
        ull S2  = pk2(j2.z, j2.z);
        #pragma unroll
        for (int p = 0; p < NP; p++){
            ull q = ffma2(L2v, vy2[p], K2);
            q = ffma2(L1v, vx2 [p], q);
            q = ffma2(C2,  vyy2[p], q);
            q = ffma2(B2,  vxy2[p], q);
            q = ffma2(A2,  vxx2[p], q);
            float ql, qh; upk2(ql, qh, q);
            ull e = pk2(ex2f(ql), ex2f(qh));
            acc2[p] = ffma2(S2, e, acc2[p]);
        }
    }

    float* out = gAcc(chunk);
    #pragma unroll
    for (int p = 0; p < NP; p++){
        float a0, a1; upk2(a0, a1, acc2[p]);
        out[base + threadIdx.x + (2*p+0)*BLOCK] = a0;
        out[base + threadIdx.x + (2*p+1)*BLOCK] = a1;
    }
}

// ---------------------------------------------------------------------------
// Full-parallel collapse: sum CH partial slots, relu_fit weight update, and
// precompute per-element scalars for the narrow tail kernels.
//   MODE 0 (topk layers): gAcc(0)[i] = score = |wn|*sqrt(clip(det))
//   MODE 1 (layer 2):     gAcc(0)[i] = u = wn*2pi*sqrt(clip(det)),
//                         gAcc(1)[i] = 0.5*(c00+c11)  (trace/D)
// ---------------------------------------------------------------------------
template<int CH, int MODE>
__global__ void collapse_kernel(int total)
{
    int i = blockIdx.x*blockDim.x + threadIdx.x;
    if (i >= total) return;
    float s = 0.f;
    #pragma unroll
    for (int c = 0; c < CH; c++) s += gAcc(c)[i];
    float w = gW()[i];
    float denom = (fabsf(s) > 1e-6f) ? s : 1e-6f;
    float wn = w * (fmaxf(s, 0.f)/denom);
    gW()[i] = wn;
    float c00 = gC00()[i], c01 = gC01()[i], c11 = gC11()[i];
    float sq = sqrtf(fmaxf(c00*c11 - c01*c01, 1e-12f));
    if (MODE == 0){
        gAcc(0)[i] = fabsf(wn)*sq;
    } else {
        gAcc(0)[i] = wn*TWO_PI_F*sq;
        gAcc(1)[i] = 0.5f*(c00 + c11);
    }
}

// ---------------------------------------------------------------------------
// Top-k (warp per batch) + channel-wise CovScaleNorm + WeightBatchNorm.
// Scores precomputed by collapse; only selected components are gathered.
// ---------------------------------------------------------------------------
template<int Co, int N, int K>
__global__ void __launch_bounds__(512) topknorm_kernel()
{
    constexpr int B = 8, BLOCK = 512;
    int co = blockIdx.x, tid = threadIdx.x;

    __shared__ float sSc[B*N];
    __shared__ int   sel[B*K];
    __shared__ float red[BLOCK];
    __shared__ float sF, sWS;

    for (int e = tid; e < B*N; e += BLOCK){
        int b = e / N, n = e - b*N;
        sSc[e] = gAcc(0)[(size_t)(b*Co + co)*N + n];
    }
    __syncthreads();

    int lane = tid & 31, wid = tid >> 5;
    if (wid < B){
        float* sc = sSc + wid*N;
        for (int it = 0; it < K; it++){
            float bv = -1.f; int bi = 1 << 30;
            for (int j = lane; j < N; j += 32){
                float v = sc[j];
                if (v > bv || (v == bv && j < bi)){ bv = v; bi = j; }
            }
            #pragma unroll
            for (int off = 16; off; off >>= 1){
                float ov = __shfl_down_sync(0xffffffffu, bv, off);
                int   oi = __shfl_down_sync(0xffffffffu, bi, off);
                if (ov > bv || (ov == bv && oi < bi)){ bv = ov; bi = oi; }
            }
            if (lane == 0){ sel[wid*K + it] = bi; sc[bi] = -2.f; }
            __syncwarp();
        }
    }
    __syncthreads();

    float tr = 0.f;
    if (tid < B*K){
        int b = tid / K; int n = sel[tid];
        size_t idx = (size_t)(b*Co + co)*N + n;
        tr = 0.5f*(gC00()[idx] + gC11()[idx]);
    }
    red[tid] = tr; __syncthreads();
    for (int s = BLOCK>>1; s; s >>= 1){ if (tid < s) red[tid] += red[tid+s]; __syncthreads(); }
    if (tid == 0) sF = rsqrtf(red[0]/(float)(B*K) + 1e-8f);
    __syncthreads();
    float f = sF, f2 = f*f;

    float ab = 0.f;
    if (tid < B*K){
        int b = tid / K; int n = sel[tid];
        size_t idx = (size_t)(b*Co + co)*N + n;
        float a = gC00()[idx]*f2, o = gC01()[idx]*f2, c = gC11()[idx]*f2;
        float det = a*c - o*o;
        ab = fabsf(gW()[idx])*TWO_PI_F*sqrtf(fmaxf(det, 1e-12f));
    }
    red[tid] = ab; __syncthreads();
    for (int s = BLOCK>>1; s; s >>= 1){ if (tid < s) red[tid] += red[tid+s]; __syncthreads(); }
    if (tid == 0) sWS = red[0]/(float)(B*K) + 1e-6f;
    __syncthreads();
    float ws = sWS;

    if (tid < B*K){
        int b = tid / K, t = tid - b*K; int n = sel[tid];
        size_t idx = (size_t)(b*Co + co)*N + n;
        size_t oi  = (size_t)(b*Co + co)*K + t;
        gA(0)[oi] = gW()[idx]/ws;
        gA(1)[oi] = gP0()[idx]*f;   gA(2)[oi] = gP1()[idx]*f;
        gA(3)[oi] = gC00()[idx]*f2; gA(4)[oi] = gC01()[idx]*f2; gA(5)[oi] = gC11()[idx]*f2;
    }
}

// ---------------------------------------------------------------------------
// Layer2 tail: channel norms + integrate from precomputed (u, tr).
//   iv = f2 * u  (det scales by f2^2 under C *= f2)
// ---------------------------------------------------------------------------
template<int Co, int N>
__global__ void __launch_bounds__(512) norm2int_kernel()
{
    constexpr int B = 8, BLOCK = 512;
    int co = blockIdx.x, tid = threadIdx.x;
    int lane = tid & 31, wid = tid >> 5;
    __shared__ float red[BLOCK];
    __shared__ float sF, sXb[B], sAb[B];

    float tr = 0.f;
    for (int e = tid; e < B*N; e += BLOCK){
        int b = e / N, n = e - b*N;
        tr += gAcc(1)[(size_t)(b*Co + co)*N + n];
    }
    red[tid] = tr; __syncthreads();
    for (int s = BLOCK>>1; s; s >>= 1){ if (tid < s) red[tid] += red[tid+s]; __syncthreads(); }
    if (tid == 0) sF = rsqrtf(red[0]/(float)(B*N) + 1e-8f);
    __syncthreads();
    float f2 = sF*sF;

    if (wid < B){
        int b = wid;
        float su = 0.f, sa = 0.f;
        for (int n = lane; n < N; n += 32){
            float u = gAcc(0)[(size_t)(b*Co + co)*N + n];
            su += u; sa += fabsf(u);
        }
        #pragma unroll
        for (int off = 16; off; off >>= 1){
            su += __shfl_down_sync(0xffffffffu, su, off);
            sa += __shfl_down_sync(0xffffffffu, sa, off);
        }
        if (lane == 0){ sXb[b] = su; sAb[b] = sa; }
    }
    __syncthreads();
    if (tid < B){
        float SA = sAb[0]+sAb[1]+sAb[2]+sAb[3]+sAb[4]+sAb[5]+sAb[6]+sAb[7];
        float ws = f2*SA/(float)(B*N) + 1e-6f;
        gX()[tid*10 + co] = f2*sXb[tid]/ws;
    }
}

// ---------------------------------------------------------------------------
// Final BatchNorm1d + log_softmax.
// ---------------------------------------------------------------------------
__global__ void final_kernel(float* __restrict__ out)
{
    __shared__ float sx[80], sn2[80];
    int t = threadIdx.x;
    if (t < 80) sx[t] = gX()[t];
    __syncthreads();
    if (t < 10){
        float mu = 0.f;
        for (int b = 0; b < 8; b++) mu += sx[b*10+t];
        mu *= 0.125f;
        float var = 0.f;
        for (int b = 0; b < 8; b++){ float d = sx[b*10+t] - mu; var += d*d; }
        var *= 0.125f;
        float iv = rsqrtf(var + 1e-5f);
        for (int b = 0; b < 8; b++) sn2[b*10+t] = (sx[b*10+t] - mu)*iv;
    }
    __syncthreads();
    if (t < 8){
        float mx = -1e30f;
        for (int c = 0; c < 10; c++) mx = fmaxf(mx, sn2[t*10+c]);
        float se = 0.f;
        for (int c = 0; c < 10; c++) se += expf(sn2[t*10+c] - mx);
        float lse = mx + logf(se);
        for (int c = 0; c < 10; c++) out[t*10+c] = sn2[t*10+c] - lse;
    }
}

// ---------------------------------------------------------------------------
extern "C" void kernel_launch(void* const* d_in, const int* in_sizes, int n_in,
                              void* d_out, int out_size)
{
    const float* in_w = (const float*)d_in[0];
    const float* in_p = (const float*)d_in[1];
    const float* in_c = (const float*)d_in[2];
    const float* k0w  = (const float*)d_in[3];
    const float* k0p  = (const float*)d_in[4];
    const float* k0c  = (const float*)d_in[5];
    const float* k1w  = (const float*)d_in[6];
    const float* k1p  = (const float*)d_in[7];
    const float* k1c  = (const float*)d_in[8];
    const float* k2w  = (const float*)d_in[9];
    const float* k2p  = (const float*)d_in[10];
    const float* k2c  = (const float*)d_in[11];
    float* out = (float*)d_out;

    norm0_kernel<<<8, 128>>>(in_w, in_p, in_c);

    // layer 0: N=640, n_fit=32; BLOCK=64, IPT=10, CH=8 -> grid 512
    eval_fused_kernel<1,128,8,5, 640,8,64,10><<<64*8, 64>>>(k0w, k0p, k0c);
    collapse_kernel<8,0><<<(64*640 + 255)/256, 256>>>(64*640);
    topknorm_kernel<8,640,32><<<8, 512>>>();

    // layer 1: N=1280, n_fit=16; BLOCK=128, IPT=10, CH=8 -> grid 1024 (1.01 imbalance)
    eval_fused_kernel<8,32,16,5, 1280,8,128,10><<<128*8, 128>>>(k1w, k1p, k1c);
    collapse_kernel<8,0><<<(128*1280 + 255)/256, 256>>>(128*1280);
    topknorm_kernel<16,1280,16><<<16, 512>>>();

    // layer 2: N=1280, keep all; BLOCK=128, IPT=10, CH=16 -> grid 1280 (1.04 imbalance)
    eval_fused_kernel<16,16,10,5, 1280,16,128,10><<<80*16, 128>>>(k2w, k2p, k2c);
    collapse_kernel<16,1><<<(80*1280 + 255)/256, 256>>>(80*1280);
    norm2int_kernel<10,1280><<<10, 512>>>();

    final_kernel<<<1, 128>>>(out);
}

// round 9
// speedup vs baseline: 2.5342x; 1.0273x over previous
#include <cuda_runtime.h>
#include <math.h>

#define TWO_PI_F 6.283185307179586f
#define L2E_F    1.4426950408889634f

typedef unsigned long long ull;

// ---------------------------------------------------------------------------
// Scratch (single __device__ array)
// ---------------------------------------------------------------------------
constexpr int NBUF = 163840;   // max pairs*N = 128*1280 (layer1)
constexpr int NA   = 2048;     // max B*Co*K

__device__ float g_scratch[(size_t)22*NBUF + 6*NA + 512];

__device__ __forceinline__ float* gW()        { return g_scratch + 0*(size_t)NBUF; }
__device__ __forceinline__ float* gP0()       { return g_scratch + 1*(size_t)NBUF; }
__device__ __forceinline__ float* gP1()       { return g_scratch + 2*(size_t)NBUF; }
__device__ __forceinline__ float* gC00()      { return g_scratch + 3*(size_t)NBUF; }
__device__ __forceinline__ float* gC01()      { return g_scratch + 4*(size_t)NBUF; }
__device__ __forceinline__ float* gC11()      { return g_scratch + 5*(size_t)NBUF; }
__device__ __forceinline__ float* gAcc(int c) { return g_scratch + (size_t)(6+c)*NBUF; }
__device__ __forceinline__ float* gA(int k)   { return g_scratch + 22*(size_t)NBUF + (size_t)k*NA; }
__device__ __forceinline__ float* gX()        { return g_scratch + 22*(size_t)NBUF + 6*(size_t)NA; }
__device__ __forceinline__ float* gY()        { return gX() + 96; }   // [10][8][3] partials

__device__ __forceinline__ float ex2f(float x){
    float r; asm("ex2.approx.ftz.f32 %0, %1;" : "=f"(r) : "f"(x)); return r;
}
__device__ __forceinline__ ull pk2(float lo, float hi){
    ull r; asm("mov.b64 %0, {%1, %2};" : "=l"(r) : "f"(lo), "f"(hi)); return r;
}
__device__ __forceinline__ void upk2(float& lo, float& hi, ull v){
    asm("mov.b64 {%0, %1}, %2;" : "=f"(lo), "=f"(hi) : "l"(v));
}
__device__ __forceinline__ ull ffma2(ull a, ull b, ull c){
    ull d; asm("fma.rn.f32x2 %0, %1, %2, %3;" : "=l"(d) : "l"(a), "l"(b), "l"(c)); return d;
}

// ---------------------------------------------------------------------------
// norm0: per-sample CovScaleNorm + WeightNorm on input GM (L=1, N=128)
// ---------------------------------------------------------------------------
__global__ void norm0_kernel(const float* __restrict__ in_w,
                             const float* __restrict__ in_p,
                             const float* __restrict__ in_c)
{
    const int N = 128;
    int b = blockIdx.x, t = threadIdx.x;
    int gi = b*N + t;
    float w  = in_w[gi];
    float px = in_p[gi*2+0], py = in_p[gi*2+1];
    float a  = in_c[gi*4+0], o = in_c[gi*4+1], c = in_c[gi*4+3];

    __shared__ float red[128];
    __shared__ float sval;

    red[t] = 0.5f*(a + c); __syncthreads();
    for (int s = N/2; s > 0; s >>= 1){ if (t < s) red[t] += red[t+s]; __syncthreads(); }
    if (t == 0) sval = rsqrtf(red[0]/(float)N + 1e-8f);
    __syncthreads();
    float f = sval, f2 = f*f;
    px *= f; py *= f; a *= f2; o *= f2; c *= f2;

    float det = a*c - o*o;
    float iv  = fabsf(w)*TWO_PI_F*sqrtf(fmaxf(det, 1e-12f));
    __syncthreads();
    red[t] = iv; __syncthreads();
    for (int s = N/2; s > 0; s >>= 1){ if (t < s) red[t] += red[t+s]; __syncthreads(); }
    if (t == 0) sval = red[0]/(float)N + 1e-6f;
    __syncthreads();
    w /= sval;

    gA(0)[gi]=w;  gA(1)[gi]=px; gA(2)[gi]=py;
    gA(3)[gi]=a;  gA(4)[gi]=o;  gA(5)[gi]=c;
}

// ---------------------------------------------------------------------------
// Fused conv + eval-at-centers, chunked over j, packed f32x2 math.
// ---------------------------------------------------------------------------
template<int Ci, int Nd, int Co, int Nk, int N, int CH, int BLOCK, int IPT>
__global__ void __launch_bounds__(BLOCK) eval_fused_kernel(
    const float* __restrict__ kw, const float* __restrict__ kp,
    const float* __restrict__ kc)
{
    static_assert(N == BLOCK*IPT, "i tiling");
    static_assert(N % CH == 0, "j chunking");
    static_assert(IPT % 2 == 0, "pairing");
    constexpr int NJ = N / CH;
    constexpr int NP = IPT/2;
    int pair  = blockIdx.x / CH;
    int chunk = blockIdx.x - pair*CH;
    int b  = pair / Co;
    int co = pair - b*Co;
    size_t base = (size_t)pair * N;

    __shared__ float4 sJ1[NJ];   // (A, B, C, K)
    __shared__ float4 sJ2[NJ];   // (L1, L2, sgn, 0)

    const float* Aw  = gA(0); const float* Ap0 = gA(1); const float* Ap1 = gA(2);
    const float* Ac00= gA(3); const float* Ac01= gA(4); const float* Ac11= gA(5);

    for (int jj = threadIdx.x; jj < NJ; jj += BLOCK){
        int n  = chunk*NJ + jj;
        int nk = n % Nk;  int t2 = n / Nk;
        int nd = t2 % Nd; int ci = t2 / Nd;
        int di = (b*Ci + ci)*Nd + nd;
        int ki = (co*Ci + ci)*Nk + nk;

        float d00=Ac00[di], d01=Ac01[di], d11=Ac11[di];
        float k00=kc[ki*4+0], k01=kc[ki*4+1], k11=kc[ki*4+3];
        float s00=d00+k00, s01=d01+k01, s11=d11+k11;

        float det_d = d00*d11 - d01*d01;
        float det_k = k00*k11 - k01*k01;
        float det_s = s00*s11 - s01*s01;
        float amp = TWO_PI_F * sqrtf(fmaxf(det_d*det_k/fmaxf(det_s,1e-12f), 1e-20f));
        float wv  = Aw[di]*kw[ki]*amp;
        float px  = Ap0[di] + kp[ki*2+0];
        float py  = Ap1[di] + kp[ki*2+1];
        float inv = 1.0f/det_s;

        float A = -0.5f*s11*inv*L2E_F;
        float Bc =  s01*inv*L2E_F;
        float Cc = -0.5f*s00*inv*L2E_F;
        float l1 = -(2.f*A*px + Bc*py);
        float l2 = -(Bc*px + 2.f*Cc*py);
        float K  = A*px*px + Bc*px*py + Cc*py*py + __log2f(fabsf(wv));
        float sg = copysignf(1.f, wv);

        sJ1[jj] = make_float4(A, Bc, Cc, K);
        sJ2[jj] = make_float4(l1, l2, sg, 0.f);

        gW()  [base+n] = wv;
        gP0() [base+n] = px;  gP1() [base+n] = py;
        gC00()[base+n] = s00; gC01()[base+n] = s01; gC11()[base+n] = s11;
    }
    __syncthreads();

    ull acc2[NP], vx2[NP], vy2[NP], vxx2[NP], vxy2[NP], vyy2[NP];
    #pragma unroll
    for (int p = 0; p < NP; p++){
        float x[2], y[2];
        #pragma unroll
        for (int h = 0; h < 2; h++){
            int i  = threadIdx.x + (2*p+h)*BLOCK;
            int nk = i % Nk;  int t2 = i / Nk;
            int nd = t2 % Nd; int ci = t2 / Nd;
            int di = (b*Ci + ci)*Nd + nd;
            int ki = (co*Ci + ci)*Nk + nk;
            x[h] = Ap0[di] + kp[ki*2+0];
            y[h] = Ap1[di] + kp[ki*2+1];
        }
        vx2 [p] = pk2(x[0],      x[1]);
        vy2 [p] = pk2(y[0],      y[1]);
        vxx2[p] = pk2(x[0]*x[0], x[1]*x[1]);
        vxy2[p] = pk2(x[0]*y[0], x[1]*y[1]);
        vyy2[p] = pk2(y[0]*y[0], y[1]*y[1]);
        acc2[p] = pk2(0.f, 0.f);
    }

    #pragma unroll 2
    for (int jj = 0; jj < NJ; jj++){
        float4 j1 = sJ1[jj];
        float4 j2 = sJ2[jj];
        ull A2  = pk2(j1.x, j1.x), B2  = pk2(j1.y, j1.y);
        ull C2  = pk2(j1.z, j1.z), K2  = pk2(j1.w, j1.w);
        ull L1v = pk2(j2.x, j2.x), L2v = pk2(j2.y, j2.y);
        ull S2  = pk2(j2.z, j2.z);
        #pragma unroll
        for (int p = 0; p < NP; p++){
            ull q = ffma2(L2v, vy2[p], K2);
            q = ffma2(L1v, vx2 [p], q);
            q = ffma2(C2,  vyy2[p], q);
            q = ffma2(B2,  vxy2[p], q);
            q = ffma2(A2,  vxx2[p], q);
            float ql, qh; upk2(ql, qh, q);
            ull e = pk2(ex2f(ql), ex2f(qh));
            acc2[p] = ffma2(S2, e, acc2[p]);
        }
    }

    float* out = gAcc(chunk);
    #pragma unroll
    for (int p = 0; p < NP; p++){
        float a0, a1; upk2(a0, a1, acc2[p]);
        out[base + threadIdx.x + (2*p+0)*BLOCK] = a0;
        out[base + threadIdx.x + (2*p+1)*BLOCK] = a1;
    }
}

// ---------------------------------------------------------------------------
// Collapse: sum CH partial slots, relu_fit weight update, precompute scalars.
//   MODE 0: gAcc(0)[i] = score;  MODE 1: gAcc(0)[i] = integrand u, gAcc(1) = tr
// ---------------------------------------------------------------------------
template<int CH, int MODE>
__global__ void collapse_kernel(int total)
{
    int i = blockIdx.x*blockDim.x + threadIdx.x;
    if (i >= total) return;
    float s = 0.f;
    #pragma unroll
    for (int c = 0; c < CH; c++) s += gAcc(c)[i];
    float w = gW()[i];
    float denom = (fabsf(s) > 1e-6f) ? s : 1e-6f;
    float wn = w * (fmaxf(s, 0.f)/denom);
    gW()[i] = wn;
    float c00 = gC00()[i], c01 = gC01()[i], c11 = gC11()[i];
    float sq = sqrtf(fmaxf(c00*c11 - c01*c01, 1e-12f));
    if (MODE == 0){
        gAcc(0)[i] = fabsf(wn)*sq;
    } else {
        gAcc(0)[i] = wn*TWO_PI_F*sq;
        gAcc(1)[i] = 0.5f*(c00 + c11);
    }
}

// ---------------------------------------------------------------------------
// Top-k select: one 32-thread block per (b,co) pair. K argmax passes over
// shared scores (jax-stable lowest-index ties), gathers selected components
// UNSCALED into compact gA layout.
// ---------------------------------------------------------------------------
template<int N, int K>
__global__ void __launch_bounds__(32) topk_sel_kernel()
{
    int pair = blockIdx.x;
    size_t ib = (size_t)pair*N, ob = (size_t)pair*K;
    __shared__ float sc[N];
    __shared__ int   sel[K];
    int lane = threadIdx.x;

    for (int j = lane; j < N; j += 32) sc[j] = gAcc(0)[ib+j];
    __syncwarp();

    for (int it = 0; it < K; it++){
        float bv = -1.f; int bi = 1 << 30;
        for (int j = lane; j < N; j += 32){
            float v = sc[j];
            if (v > bv || (v == bv && j < bi)){ bv = v; bi = j; }
        }
        #pragma unroll
        for (int off = 16; off; off >>= 1){
            float ov = __shfl_down_sync(0xffffffffu, bv, off);
            int   oi = __shfl_down_sync(0xffffffffu, bi, off);
            if (ov > bv || (ov == bv && oi < bi)){ bv = ov; bi = oi; }
        }
        bv = __shfl_sync(0xffffffffu, bv, 0);
        bi = __shfl_sync(0xffffffffu, bi, 0);
        if (lane == 0){ sel[it] = bi; sc[bi] = -2.f; }
        __syncwarp();
    }

    for (int t = lane; t < K; t += 32){
        size_t idx = ib + sel[t];
        gA(0)[ob+t] = gW()  [idx];
        gA(1)[ob+t] = gP0() [idx];
        gA(2)[ob+t] = gP1() [idx];
        gA(3)[ob+t] = gC00()[idx];
        gA(4)[ob+t] = gC01()[idx];
        gA(5)[ob+t] = gC11()[idx];
    }
}

// ---------------------------------------------------------------------------
// Channel-wise CovScaleNorm + WeightBatchNorm over the compact selected set.
// Block per channel co; one thread per element (B*K <= 256).
// ---------------------------------------------------------------------------
template<int Co, int K>
__global__ void __launch_bounds__(256) chan_norm_kernel()
{
    constexpr int B = 8, BLOCK = 256, M = B*K;
    int co = blockIdx.x, tid = threadIdx.x;
    __shared__ float red[BLOCK];
    __shared__ float sF, sWS;

    size_t oi = 0;
    float tr = 0.f;
    if (tid < M){
        int b = tid / K, t = tid - b*K;
        oi = (size_t)(b*Co + co)*K + t;
        tr = 0.5f*(gA(3)[oi] + gA(5)[oi]);
    }
    red[tid] = tr; __syncthreads();
    for (int s = BLOCK>>1; s; s >>= 1){ if (tid < s) red[tid] += red[tid+s]; __syncthreads(); }
    if (tid == 0) sF = rsqrtf(red[0]/(float)M + 1e-8f);
    __syncthreads();
    float f = sF, f2 = f*f;

    float ab = 0.f;
    if (tid < M){
        float a = gA(3)[oi]*f2, o = gA(4)[oi]*f2, c = gA(5)[oi]*f2;
        float det = a*c - o*o;
        ab = fabsf(gA(0)[oi])*TWO_PI_F*sqrtf(fmaxf(det, 1e-12f));
    }
    red[tid] = ab; __syncthreads();
    for (int s = BLOCK>>1; s; s >>= 1){ if (tid < s) red[tid] += red[tid+s]; __syncthreads(); }
    if (tid == 0) sWS = red[0]/(float)M + 1e-6f;
    __syncthreads();
    float ws = sWS;

    if (tid < M){
        gA(0)[oi] /= ws;
        gA(1)[oi] *= f;  gA(2)[oi] *= f;
        gA(3)[oi] *= f2; gA(4)[oi] *= f2; gA(5)[oi] *= f2;
    }
}

// ---------------------------------------------------------------------------
// Layer2 partials: block per (co,b), sums (tr, u, |u|) over n -> gY[co][b][3]
// ---------------------------------------------------------------------------
template<int Co, int N>
__global__ void __launch_bounds__(128) lay2part_kernel()
{
    constexpr int BLOCK = 128;
    int co = blockIdx.x >> 3, b = blockIdx.x & 7;
    int tid = threadIdx.x, lane = tid & 31, wid = tid >> 5;
    size_t base = (size_t)(b*Co + co)*N;

    float tr = 0.f, su = 0.f, sa = 0.f;
    for (int n = tid; n < N; n += BLOCK){
        float u = gAcc(0)[base+n];
        tr += gAcc(1)[base+n];
        su += u; sa += fabsf(u);
    }
    #pragma unroll
    for (int off = 16; off; off >>= 1){
        tr += __shfl_down_sync(0xffffffffu, tr, off);
        su += __shfl_down_sync(0xffffffffu, su, off);
        sa += __shfl_down_sync(0xffffffffu, sa, off);
    }
    __shared__ float w3[3][4];
    if (lane == 0){ w3[0][wid] = tr; w3[1][wid] = su; w3[2][wid] = sa; }
    __syncthreads();
    if (tid == 0){
        float* o = gY() + (size_t)(co*8 + b)*3;
        o[0] = w3[0][0]+w3[0][1]+w3[0][2]+w3[0][3];
        o[1] = w3[1][0]+w3[1][1]+w3[1][2]+w3[1][3];
        o[2] = w3[2][0]+w3[2][1]+w3[2][2]+w3[2][3];
    }
}

// ---------------------------------------------------------------------------
// Final: layer2 channel norms + integrate + BatchNorm1d + log_softmax.
// ---------------------------------------------------------------------------
template<int Co, int N>
__global__ void final_kernel(float* __restrict__ out)
{
    constexpr int B = 8;
    __shared__ float sn2[80];
    int t = threadIdx.x;
    if (t < Co){
        int co = t;
        float str = 0.f, ssa = 0.f;
        #pragma unroll
        for (int b = 0; b < B; b++){
            str += gY()[(size_t)(co*8+b)*3 + 0];
            ssa += gY()[(size_t)(co*8+b)*3 + 2];
        }
        float mtr = str/(float)(B*N);
        float fr  = rsqrtf(mtr + 1e-8f);
        float f2  = fr*fr;
        float ws  = f2*ssa/(float)(B*N) + 1e-6f;
        float x[B];
        float mu = 0.f;
        #pragma unroll
        for (int b = 0; b < B; b++){
            x[b] = f2*gY()[(size_t)(co*8+b)*3 + 1]/ws;
            mu += x[b];
        }
        mu *= 0.125f;
        float var = 0.f;
        #pragma unroll
        for (int b = 0; b < B; b++){ float d = x[b]-mu; var += d*d; }
        var *= 0.125f;
        float iv = rsqrtf(var + 1e-5f);
        #pragma unroll
        for (int b = 0; b < B; b++) sn2[b*10+co] = (x[b]-mu)*iv;
    }
    __syncthreads();
    if (t < B){
        float mx = -1e30f;
        for (int c = 0; c < 10; c++) mx = fmaxf(mx, sn2[t*10+c]);
        float se = 0.f;
        for (int c = 0; c < 10; c++) se += expf(sn2[t*10+c] - mx);
        float lse = mx + logf(se);
        for (int c = 0; c < 10; c++) out[t*10+c] = sn2[t*10+c] - lse;
    }
}

// ---------------------------------------------------------------------------
extern "C" void kernel_launch(void* const* d_in, const int* in_sizes, int n_in,
                              void* d_out, int out_size)
{
    const float* in_w = (const float*)d_in[0];
    const float* in_p = (const float*)d_in[1];
    const float* in_c = (const float*)d_in[2];
    const float* k0w  = (const float*)d_in[3];
    const float* k0p  = (const float*)d_in[4];
    const float* k0c  = (const float*)d_in[5];
    const float* k1w  = (const float*)d_in[6];
    const float* k1p  = (const float*)d_in[7];
    const float* k1c  = (const float*)d_in[8];
    const float* k2w  = (const float*)d_in[9];
    const float* k2p  = (const float*)d_in[10];
    const float* k2c  = (const float*)d_in[11];
    float* out = (float*)d_out;

    norm0_kernel<<<8, 128>>>(in_w, in_p, in_c);

    // layer 0: N=640, n_fit=32
    eval_fused_kernel<1,128,8,5, 640,8,64,10><<<64*8, 64>>>(k0w, k0p, k0c);
    collapse_kernel<8,0><<<(64*640 + 255)/256, 256>>>(64*640);
    topk_sel_kernel<640,32><<<64, 32>>>();
    chan_norm_kernel<8,32><<<8, 256>>>();

    // layer 1: N=1280, n_fit=16
    eval_fused_kernel<8,32,16,5, 1280,8,128,10><<<128*8, 128>>>(k1w, k1p, k1c);
    collapse_kernel<8,0><<<(128*1280 + 255)/256, 256>>>(128*1280);
    topk_sel_kernel<1280,16><<<128, 32>>>();
    chan_norm_kernel<16,16><<<16, 256>>>();

    // layer 2: N=1280, keep all
    eval_fused_kernel<16,16,10,5, 1280,16,128,10><<<80*16, 128>>>(k2w, k2p, k2c);
    collapse_kernel<16,1><<<(80*1280 + 255)/256, 256>>>(80*1280);
    lay2part_kernel<10,1280><<<80, 128>>>();
    final_kernel<10,1280><<<1, 128>>>(out);
}

// round 14
// speedup vs baseline: 2.9114x; 1.1488x over previous
#include <cuda_runtime.h>
#include <math.h>

#define TWO_PI_F 6.283185307179586f
#define L2E_F    1.4426950408889634f

typedef unsigned long long ull;

// ---------------------------------------------------------------------------
// Scratch (single __device__ array)
// ---------------------------------------------------------------------------
constexpr int NBUF = 163840;   // max pairs*N = 128*1280 (layer1)
constexpr int NA   = 2048;     // max B*Co*K

__device__ float g_scratch[(size_t)22*NBUF + 6*NA + 512];

__device__ __forceinline__ float* gW()        { return g_scratch + 0*(size_t)NBUF; }
__device__ __forceinline__ float* gP0()       { return g_scratch + 1*(size_t)NBUF; }
__device__ __forceinline__ float* gP1()       { return g_scratch + 2*(size_t)NBUF; }
__device__ __forceinline__ float* gC00()      { return g_scratch + 3*(size_t)NBUF; }
__device__ __forceinline__ float* gC01()      { return g_scratch + 4*(size_t)NBUF; }
__device__ __forceinline__ float* gC11()      { return g_scratch + 5*(size_t)NBUF; }
__device__ __forceinline__ float* gAcc(int c) { return g_scratch + (size_t)(6+c)*NBUF; }
__device__ __forceinline__ float* gA(int k)   { return g_scratch + 22*(size_t)NBUF + (size_t)k*NA; }
__device__ __forceinline__ float* gX()        { return g_scratch + 22*(size_t)NBUF + 6*(size_t)NA; }
__device__ __forceinline__ float* gY()        { return gX() + 96; }   // [10][8][3] partials

__device__ __forceinline__ float ex2f(float x){
    float r; asm("ex2.approx.ftz.f32 %0, %1;" : "=f"(r) : "f"(x)); return r;
}
__device__ __forceinline__ ull pk2(float lo, float hi){
    ull r; asm("mov.b64 %0, {%1, %2};" : "=l"(r) : "f"(lo), "f"(hi)); return r;
}
__device__ __forceinline__ void upk2(float& lo, float& hi, ull v){
    asm("mov.b64 {%0, %1}, %2;" : "=f"(lo), "=f"(hi) : "l"(v));
}
__device__ __forceinline__ ull ffma2(ull a, ull b, ull c){
    ull d; asm("fma.rn.f32x2 %0, %1, %2, %3;" : "=l"(d) : "l"(a), "l"(b), "l"(c)); return d;
}
__device__ __forceinline__ ull umax64(ull a, ull b){ return a > b ? a : b; }

// ---------------------------------------------------------------------------
// norm0: per-sample CovScaleNorm + WeightNorm on input GM (L=1, N=128)
// ---------------------------------------------------------------------------
__global__ void norm0_kernel(const float* __restrict__ in_w,
                             const float* __restrict__ in_p,
                             const float* __restrict__ in_c)
{
    const int N = 128;
    int b = blockIdx.x, t = threadIdx.x;
    int gi = b*N + t;
    float w  = in_w[gi];
    float px = in_p[gi*2+0], py = in_p[gi*2+1];
    float a  = in_c[gi*4+0], o = in_c[gi*4+1], c = in_c[gi*4+3];

    __shared__ float red[128];
    __shared__ float sval;

    red[t] = 0.5f*(a + c); __syncthreads();
    for (int s = N/2; s > 0; s >>= 1){ if (t < s) red[t] += red[t+s]; __syncthreads(); }
    if (t == 0) sval = rsqrtf(red[0]/(float)N + 1e-8f);
    __syncthreads();
    float f = sval, f2 = f*f;
    px *= f; py *= f; a *= f2; o *= f2; c *= f2;

    float det = a*c - o*o;
    float iv  = fabsf(w)*TWO_PI_F*sqrtf(fmaxf(det, 1e-12f));
    __syncthreads();
    red[t] = iv; __syncthreads();
    for (int s = N/2; s > 0; s >>= 1){ if (t < s) red[t] += red[t+s]; __syncthreads(); }
    if (t == 0) sval = red[0]/(float)N + 1e-6f;
    __syncthreads();
    w /= sval;

    gA(0)[gi]=w;  gA(1)[gi]=px; gA(2)[gi]=py;
    gA(3)[gi]=a;  gA(4)[gi]=o;  gA(5)[gi]=c;
}

// ---------------------------------------------------------------------------
// Fused conv + eval-at-centers, chunked over j, packed f32x2 math.
// ---------------------------------------------------------------------------
template<int Ci, int Nd, int Co, int Nk, int N, int CH, int BLOCK, int IPT>
__global__ void __launch_bounds__(BLOCK) eval_fused_kernel(
    const float* __restrict__ kw, const float* __restrict__ kp,
    const float* __restrict__ kc)
{
    static_assert(N == BLOCK*IPT, "i tiling");
    static_assert(N % CH == 0, "j chunking");
    static_assert(IPT % 2 == 0, "pairing");
    constexpr int NJ = N / CH;
    constexpr int NP = IPT/2;
    int pair  = blockIdx.x / CH;
    int chunk = blockIdx.x - pair*CH;
    int b  = pair / Co;
    int co = pair - b*Co;
    size_t base = (size_t)pair * N;

    __shared__ float4 sJ1[NJ];   // (A, B, C, K)
    __shared__ float4 sJ2[NJ];   // (L1, L2, sgn, 0)

    const float* Aw  = gA(0); const float* Ap0 = gA(1); const float* Ap1 = gA(2);
    const float* Ac00= gA(3); const float* Ac01= gA(4); const float* Ac11= gA(5);

    for (int jj = threadIdx.x; jj < NJ; jj += BLOCK){
        int n  = chunk*NJ + jj;
        int nk = n % Nk;  int t2 = n / Nk;
        int nd = t2 % Nd; int ci = t2 / Nd;
        int di = (b*Ci + ci)*Nd + nd;
        int ki = (co*Ci + ci)*Nk + nk;

        float d00=Ac00[di], d01=Ac01[di], d11=Ac11[di];
        float k00=kc[ki*4+0], k01=kc[ki*4+1], k11=kc[ki*4+3];
        float s00=d00+k00, s01=d01+k01, s11=d11+k11;

        float det_d = d00*d11 - d01*d01;
        float det_k = k00*k11 - k01*k01;
        float det_s = s00*s11 - s01*s01;
        float amp = TWO_PI_F * sqrtf(fmaxf(det_d*det_k/fmaxf(det_s,1e-12f), 1e-20f));
        float wv  = Aw[di]*kw[ki]*amp;
        float px  = Ap0[di] + kp[ki*2+0];
        float py  = Ap1[di] + kp[ki*2+1];
        float inv = 1.0f/det_s;

        float A = -0.5f*s11*inv*L2E_F;
        float Bc =  s01*inv*L2E_F;
        float Cc = -0.5f*s00*inv*L2E_F;
        float l1 = -(2.f*A*px + Bc*py);
        float l2 = -(Bc*px + 2.f*Cc*py);
        float K  = A*px*px + Bc*px*py + Cc*py*py + __log2f(fabsf(wv));
        float sg = copysignf(1.f, wv);

        sJ1[jj] = make_float4(A, Bc, Cc, K);
        sJ2[jj] = make_float4(l1, l2, sg, 0.f);

        gW()  [base+n] = wv;
        gP0() [base+n] = px;  gP1() [base+n] = py;
        gC00()[base+n] = s00; gC01()[base+n] = s01; gC11()[base+n] = s11;
    }
    __syncthreads();

    ull acc2[NP], vx2[NP], vy2[NP], vxx2[NP], vxy2[NP], vyy2[NP];
    #pragma unroll
    for (int p = 0; p < NP; p++){
        float x[2], y[2];
        #pragma unroll
        for (int h = 0; h < 2; h++){
            int i  = threadIdx.x + (2*p+h)*BLOCK;
            int nk = i % Nk;  int t2 = i / Nk;
            int nd = t2 % Nd; int ci = t2 / Nd;
            int di = (b*Ci + ci)*Nd + nd;
            int ki = (co*Ci + ci)*Nk + nk;
            x[h] = Ap0[di] + kp[ki*2+0];
            y[h] = Ap1[di] + kp[ki*2+1];
        }
        vx2 [p] = pk2(x[0],      x[1]);
        vy2 [p] = pk2(y[0],      y[1]);
        vxx2[p] = pk2(x[0]*x[0], x[1]*x[1]);
        vxy2[p] = pk2(x[0]*y[0], x[1]*y[1]);
        vyy2[p] = pk2(y[0]*y[0], y[1]*y[1]);
        acc2[p] = pk2(0.f, 0.f);
    }

    #pragma unroll 2
    for (int jj = 0; jj < NJ; jj++){
        float4 j1 = sJ1[jj];
        float4 j2 = sJ2[jj];
        ull A2  = pk2(j1.x, j1.x), B2  = pk2(j1.y, j1.y);
        ull C2  = pk2(j1.z, j1.z), K2  = pk2(j1.w, j1.w);
        ull L1v = pk2(j2.x, j2.x), L2v = pk2(j2.y, j2.y);
        ull S2  = pk2(j2.z, j2.z);
        #pragma unroll
        for (int p = 0; p < NP; p++){
            ull q = ffma2(L2v, vy2[p], K2);
            q = ffma2(L1v, vx2 [p], q);
            q = ffma2(C2,  vyy2[p], q);
            q = ffma2(B2,  vxy2[p], q);
            q = ffma2(A2,  vxx2[p], q);
            float ql, qh; upk2(ql, qh, q);
            ull e = pk2(ex2f(ql), ex2f(qh));
            acc2[p] = ffma2(S2, e, acc2[p]);
        }
    }

    float* out = gAcc(chunk);
    #pragma unroll
    for (int p = 0; p < NP; p++){
        float a0, a1; upk2(a0, a1, acc2[p]);
        out[base + threadIdx.x + (2*p+0)*BLOCK] = a0;
        out[base + threadIdx.x + (2*p+1)*BLOCK] = a1;
    }
}

// ---------------------------------------------------------------------------
// Collapse: sum CH partial slots, relu_fit weight update, precompute scalars.
//   MODE 0: gAcc(0)[i] = score;  MODE 1: gAcc(0)[i] = integrand u, gAcc(1) = tr
// ---------------------------------------------------------------------------
template<int CH, int MODE>
__global__ void collapse_kernel(int total)
{
    int i = blockIdx.x*blockDim.x + threadIdx.x;
    if (i >= total) return;
    float s = 0.f;
    #pragma unroll
    for (int c = 0; c < CH; c++) s += gAcc(c)[i];
    float w = gW()[i];
    float denom = (fabsf(s) > 1e-6f) ? s : 1e-6f;
    float wn = w * (fmaxf(s, 0.f)/denom);
    gW()[i] = wn;
    float c00 = gC00()[i], c01 = gC01()[i], c11 = gC11()[i];
    float sq = sqrtf(fmaxf(c00*c11 - c01*c01, 1e-12f));
    if (MODE == 0){
        gAcc(0)[i] = fabsf(wn)*sq;
    } else {
        gAcc(0)[i] = wn*TWO_PI_F*sq;
        gAcc(1)[i] = 0.5f*(c00 + c11);
    }
}

// ---------------------------------------------------------------------------
// Top-k select: one warp per (b,co) pair, register-resident scores packed as
// u64 = (score_bits << 32) | ~index. Max over u64 = (max score, lowest index
// on ties) — identical to jax.lax.top_k semantics for nonnegative scores.
// ---------------------------------------------------------------------------
template<int N, int K>
__global__ void __launch_bounds__(32) topk_sel_kernel()
{
    constexpr int R = N/32;
    static_assert(N == R*32, "exact");
    int pair = blockIdx.x;
    size_t ib = (size_t)pair*N, ob = (size_t)pair*K;
    int lane = threadIdx.x;

    ull v[R];
    #pragma unroll
    for (int r = 0; r < R; r++){
        int j = lane + r*32;
        float s = gAcc(0)[ib+j];
        v[r] = ((ull)__float_as_uint(s) << 32) | (ull)(unsigned)(~j);
    }

    __shared__ int sel[K];

    for (int it = 0; it < K; it++){
        // 4 independent local chains, then combine
        ull m0 = v[0], m1 = v[1], m2 = v[2], m3 = v[3];
        #pragma unroll
        for (int r = 4; r < R; r += 4){
            m0 = umax64(m0, v[r]);
            if (r+1 < R) m1 = umax64(m1, v[r+1]);
            if (r+2 < R) m2 = umax64(m2, v[r+2]);
            if (r+3 < R) m3 = umax64(m3, v[r+3]);
        }
        ull m = umax64(umax64(m0, m1), umax64(m2, m3));
        // warp reduce
        #pragma unroll
        for (int off = 16; off; off >>= 1)
            m = umax64(m, __shfl_down_sync(0xffffffffu, m, off));
        m = __shfl_sync(0xffffffffu, m, 0);
        // clear winner (exact packed match is unique: index is embedded)
        #pragma unroll
        for (int r = 0; r < R; r++) if (v[r] == m) v[r] = 0;
        if (lane == 0) sel[it] = (int)(unsigned)~((unsigned)(m & 0xffffffffu));
    }
    __syncwarp();

    for (int t = lane; t < K; t += 32){
        size_t idx = ib + sel[t];
        gA(0)[ob+t] = gW()  [idx];
        gA(1)[ob+t] = gP0() [idx];
        gA(2)[ob+t] = gP1() [idx];
        gA(3)[ob+t] = gC00()[idx];
        gA(4)[ob+t] = gC01()[idx];
        gA(5)[ob+t] = gC11()[idx];
    }
}

// ---------------------------------------------------------------------------
// Channel-wise CovScaleNorm + WeightBatchNorm over the compact selected set.
// Block per channel co; one thread per element (B*K <= 256).
// ---------------------------------------------------------------------------
template<int Co, int K>
__global__ void __launch_bounds__(256) chan_norm_kernel()
{
    constexpr int B = 8, BLOCK = 256, M = B*K;
    int co = blockIdx.x, tid = threadIdx.x;
    __shared__ float red[BLOCK];
    __shared__ float sF, sWS;

    size_t oi = 0;
    float tr = 0.f;
    if (tid < M){
        int b = tid / K, t = tid - b*K;
        oi = (size_t)(b*Co + co)*K + t;
        tr = 0.5f*(gA(3)[oi] + gA(5)[oi]);
    }
    red[tid] = tr; __syncthreads();
    for (int s = BLOCK>>1; s; s >>= 1){ if (tid < s) red[tid] += red[tid+s]; __syncthreads(); }
    if (tid == 0) sF = rsqrtf(red[0]/(float)M + 1e-8f);
    __syncthreads();
    float f = sF, f2 = f*f;

    float ab = 0.f;
    if (tid < M){
        float a = gA(3)[oi]*f2, o = gA(4)[oi]*f2, c = gA(5)[oi]*f2;
        float det = a*c - o*o;
        ab = fabsf(gA(0)[oi])*TWO_PI_F*sqrtf(fmaxf(det, 1e-12f));
    }
    red[tid] = ab; __syncthreads();
    for (int s = BLOCK>>1; s; s >>= 1){ if (tid < s) red[tid] += red[tid+s]; __syncthreads(); }
    if (tid == 0) sWS = red[0]/(float)M + 1e-6f;
    __syncthreads();
    float ws = sWS;

    if (tid < M){
        gA(0)[oi] /= ws;
        gA(1)[oi] *= f;  gA(2)[oi] *= f;
        gA(3)[oi] *= f2; gA(4)[oi] *= f2; gA(5)[oi] *= f2;
    }
}

// ---------------------------------------------------------------------------
// Layer2 partials: block per (co,b), sums (tr, u, |u|) over n -> gY[co][b][3]
// ---------------------------------------------------------------------------
template<int Co, int N>
__global__ void __launch_bounds__(128) lay2part_kernel()
{
    constexpr int BLOCK = 128;
    int co = blockIdx.x >> 3, b = blockIdx.x & 7;
    int tid = threadIdx.x, lane = tid & 31, wid = tid >> 5;
    size_t base = (size_t)(b*Co + co)*N;

    float tr = 0.f, su = 0.f, sa = 0.f;
    for (int n = tid; n < N; n += BLOCK){
        float u = gAcc(0)[base+n];
        tr += gAcc(1)[base+n];
        su += u; sa += fabsf(u);
    }
    #pragma unroll
    for (int off = 16; off; off >>= 1){
        tr += __shfl_down_sync(0xffffffffu, tr, off);
        su += __shfl_down_sync(0xffffffffu, su, off);
        sa += __shfl_down_sync(0xffffffffu, sa, off);
    }
    __shared__ float w3[3][4];
    if (lane == 0){ w3[0][wid] = tr; w3[1][wid] = su; w3[2][wid] = sa; }
    __syncthreads();
    if (tid == 0){
        float* o = gY() + (size_t)(co*8 + b)*3;
        o[0] = w3[0][0]+w3[0][1]+w3[0][2]+w3[0][3];
        o[1] = w3[1][0]+w3[1][1]+w3[1][2]+w3[1][3];
        o[2] = w3[2][0]+w3[2][1]+w3[2][2]+w3[2][3];
    }
}

// ---------------------------------------------------------------------------
// Final: layer2 channel norms + integrate + BatchNorm1d + log_softmax.
// ---------------------------------------------------------------------------
template<int Co, int N>
__global__ void final_kernel(float* __restrict__ out)
{
    constexpr int B = 8;
    __shared__ float sn2[80];
    int t = threadIdx.x;
    if (t < Co){
        int co = t;
        float str = 0.f, ssa = 0.f;
        #pragma unroll
        for (int b = 0; b < B; b++){
            str += gY()[(size_t)(co*8+b)*3 + 0];
            ssa += gY()[(size_t)(co*8+b)*3 + 2];
        }
        float mtr = str/(float)(B*N);
        float fr  = rsqrtf(mtr + 1e-8f);
        float f2  = fr*fr;
        float ws  = f2*ssa/(float)(B*N) + 1e-6f;
        float x[B];
        float mu = 0.f;
        #pragma unroll
        for (int b = 0; b < B; b++){
            x[b] = f2*gY()[(size_t)(co*8+b)*3 + 1]/ws;
            mu += x[b];
        }
        mu *= 0.125f;
        float var = 0.f;
        #pragma unroll
        for (int b = 0; b < B; b++){ float d = x[b]-mu; var += d*d; }
        var *= 0.125f;
        float iv = rsqrtf(var + 1e-5f);
        #pragma unroll
        for (int b = 0; b < B; b++) sn2[b*10+co] = (x[b]-mu)*iv;
    }
    __syncthreads();
    if (t < B){
        float mx = -1e30f;
        for (int c = 0; c < 10; c++) mx = fmaxf(mx, sn2[t*10+c]);
        float se = 0.f;
        for (int c = 0; c < 10; c++) se += expf(sn2[t*10+c] - mx);
        float lse = mx + logf(se);
        for (int c = 0; c < 10; c++) out[t*10+c] = sn2[t*10+c] - lse;
    }
}

// ---------------------------------------------------------------------------
extern "C" void kernel_launch(void* const* d_in, const int* in_sizes, int n_in,
                              void* d_out, int out_size)
{
    const float* in_w = (const float*)d_in[0];
    const float* in_p = (const float*)d_in[1];
    const float* in_c = (const float*)d_in[2];
    const float* k0w  = (const float*)d_in[3];
    const float* k0p  = (const float*)d_in[4];
    const float* k0c  = (const float*)d_in[5];
    const float* k1w  = (const float*)d_in[6];
    const float* k1p  = (const float*)d_in[7];
    const float* k1c  = (const float*)d_in[8];
    const float* k2w  = (const float*)d_in[9];
    const float* k2p  = (const float*)d_in[10];
    const float* k2c  = (const float*)d_in[11];
    float* out = (float*)d_out;

    norm0_kernel<<<8, 128>>>(in_w, in_p, in_c);

    // layer 0: N=640, n_fit=32
    eval_fused_kernel<1,128,8,5, 640,8,64,10><<<64*8, 64>>>(k0w, k0p, k0c);
    collapse_kernel<8,0><<<(64*640 + 255)/256, 256>>>(64*640);
    topk_sel_kernel<640,32><<<64, 32>>>();
    chan_norm_kernel<8,32><<<8, 256>>>();

    // layer 1: N=1280, n_fit=16
    eval_fused_kernel<8,32,16,5, 1280,8,128,10><<<128*8, 128>>>(k1w, k1p, k1c);
    collapse_kernel<8,0><<<(128*1280 + 255)/256, 256>>>(128*1280);
    topk_sel_kernel<1280,16><<<128, 32>>>();
    chan_norm_kernel<16,16><<<16, 256>>>();

    // layer 2: N=1280, keep all
    eval_fused_kernel<16,16,10,5, 1280,16,128,10><<<80*16, 128>>>(k2w, k2p, k2c);
    collapse_kernel<16,1><<<(80*1280 + 255)/256, 256>>>(80*1280);
    lay2part_kernel<10,1280><<<80, 128>>>();
    final_kernel<10,1280><<<1, 128>>>(out);
}